// round 12
// baseline (speedup 1.0000x reference)
#include <cuda_runtime.h>
#include <cuda_bf16.h>
#include <cstdint>

#define BWIN 2048
#define NTOK 64
#define DIM  256
#define HEADS 8
#define HD   32
#define NW   64

// ---- scratch (device globals; no allocations allowed) ----
__device__ uint32_t g_qh[BWIN*HEADS*NTOK*16];
__device__ uint32_t g_ql[BWIN*HEADS*NTOK*16];
__device__ uint32_t g_kh[BWIN*HEADS*NTOK*16];
__device__ uint32_t g_kl[BWIN*HEADS*NTOK*16];
__device__ uint32_t g_vh[BWIN*HEADS*NTOK*16];
__device__ uint32_t g_vl[BWIN*HEADS*NTOK*16];
__device__ float    g_qn[BWIN*HEADS*NTOK];
__device__ float    g_kn[BWIN*HEADS*NTOK];
__device__ float g_ao[BWIN*NTOK*DIM];
__device__ float g_bias  [HEADS*NTOK*NTOK];
__device__ float g_invtau[HEADS*NTOK*NTOK];
__device__ __nv_bfloat16 g_wbh[262144];
__device__ __nv_bfloat16 g_wbl[262144];

// ============================================================
// helpers
// ============================================================
__device__ __forceinline__ void mma16816(float* c, const uint32_t* a, const uint32_t* b) {
    asm volatile("mma.sync.aligned.m16n8k16.row.col.f32.bf16.bf16.f32 "
        "{%0,%1,%2,%3}, {%4,%5,%6,%7}, {%8,%9}, {%0,%1,%2,%3};\n"
        : "+f"(c[0]), "+f"(c[1]), "+f"(c[2]), "+f"(c[3])
        : "r"(a[0]), "r"(a[1]), "r"(a[2]), "r"(a[3]), "r"(b[0]), "r"(b[1]));
}
__device__ __forceinline__ void ldsm_x2(uint32_t* r, uint32_t addr) {
    asm volatile("ldmatrix.sync.aligned.m8n8.x2.shared.b16 {%0,%1}, [%2];"
        : "=r"(r[0]), "=r"(r[1]) : "r"(addr));
}
__device__ __forceinline__ void ldsm_x2t(uint32_t* r, uint32_t addr) {
    asm volatile("ldmatrix.sync.aligned.m8n8.x2.trans.shared.b16 {%0,%1}, [%2];"
        : "=r"(r[0]), "=r"(r[1]) : "r"(addr));
}
__device__ __forceinline__ void cp16(uint32_t smem, const void* gmem) {
    asm volatile("cp.async.cg.shared.global [%0], [%1], 16;" :: "r"(smem), "l"(gmem));
}
__device__ __forceinline__ void cp_commit() { asm volatile("cp.async.commit_group;"); }
__device__ __forceinline__ void cp_wait0()  { asm volatile("cp.async.wait_group 0;"); }
__device__ __forceinline__ uint32_t pack_hi(float a, float b, float& ra, float& rb) {
    __nv_bfloat16 ha = __float2bfloat16_rn(a);
    __nv_bfloat16 hb = __float2bfloat16_rn(b);
    ra = a - __bfloat162float(ha);
    rb = b - __bfloat162float(hb);
    return ((uint32_t)__bfloat16_as_ushort(hb) << 16) | (uint32_t)__bfloat16_as_ushort(ha);
}
__device__ __forceinline__ uint32_t pack2(float a, float b) {
    return ((uint32_t)__bfloat16_as_ushort(__float2bfloat16_rn(b)) << 16)
         | (uint32_t)__bfloat16_as_ushort(__float2bfloat16_rn(a));
}

// ============================================================
// Kernel 0: merged weight pre-split + CPB bias + inv-tau
//   blocks 0..1023: weights; blocks 1024..1039: bias tables
// ============================================================
__global__ void prep_kernel(const float* __restrict__ Wq,
                            const float* __restrict__ Wkv,
                            const float* __restrict__ Wp,
                            const float* __restrict__ w1, const float* __restrict__ b1,
                            const float* __restrict__ w2, const float* __restrict__ b2,
                            const float* __restrict__ tau, const float* __restrict__ lri)
{
    if (blockIdx.x < 1024) {
        int i = blockIdx.x * 256 + threadIdx.x;
        float f;
        if (i < 65536) f = Wq[i];
        else if (i < 196608) f = Wkv[i - 65536];
        else f = Wp[i - 196608];
        __nv_bfloat16 hh = __float2bfloat16_rn(f);
        g_wbh[i] = hh;
        g_wbl[i] = __float2bfloat16_rn(f - __bfloat162float(hh));
    } else {
        int idx = (blockIdx.x - 1024) * 256 + threadIdx.x;
        if (idx >= NTOK*NTOK) return;
        float r0 = lri[idx*2 + 0];
        float r1 = lri[idx*2 + 1];
        float acc[HEADS];
        #pragma unroll
        for (int h = 0; h < HEADS; h++) acc[h] = 0.f;
        for (int k = 0; k < 256; k++) {
            float hk = fmaxf(r0 * w1[k] + r1 * w1[256 + k] + b1[k], 0.f);
            #pragma unroll
            for (int h = 0; h < HEADS; h++) acc[h] += hk * w2[k*HEADS + h];
        }
        #pragma unroll
        for (int h = 0; h < HEADS; h++) {
            g_bias[h*NTOK*NTOK + idx] = acc[h] + b2[h];
            g_invtau[h*NTOK*NTOK + idx] = 1.0f / fmaxf(tau[h*NTOK*NTOK + idx], 0.01f);
        }
    }
}

// ============================================================
// Kernel 2a: fused Q+KV projection GEMM (unchanged from R11)
// ============================================================
__global__ void __launch_bounds__(256, 2) qkv_gemm_kernel(
    const float* __restrict__ Aq, const float* __restrict__ Akv,
    const float* __restrict__ bq, const float* __restrict__ bkv)
{
    __shared__ alignas(16) char Bs_h[2][4096];
    __shared__ alignas(16) char Bs_l[2][4096];

    int bx = blockIdx.x;
    int mode = (bx < 2) ? 0 : 1;
    const float* A = (mode == 0) ? Aq : Akv;
    const float* bias = (mode == 0) ? bq : bkv;
    int ldb  = (mode == 0) ? 256 : 512;
    int woff = (mode == 0) ? 0 : 65536;
    int col0 = ((mode == 0) ? bx : bx - 2) * 128;

    int tid = threadIdx.x;
    int lane = tid & 31, wid = tid >> 5;
    int warp_m = wid >> 1, warp_n = wid & 1;
    int row0 = blockIdx.y * 128;

    int k_b2 = tid >> 4;
    int n_b2 = (tid & 15) * 8;
    uint32_t offB = (uint32_t)k_b2*256u + (uint32_t)(((n_b2 >> 3) ^ (k_b2 & 7)) << 4);
    uint32_t stBh[2], stBl[2];
    #pragma unroll
    for (int s = 0; s < 2; s++) {
        stBh[s] = (uint32_t)__cvta_generic_to_shared(&Bs_h[s][0]) + offB;
        stBl[s] = (uint32_t)__cvta_generic_to_shared(&Bs_l[s][0]) + offB;
    }
    int bk_lane = lane & 15;
    uint32_t bbase_h[2], bbase_l[2];
    #pragma unroll
    for (int s = 0; s < 2; s++) {
        bbase_h[s] = (uint32_t)__cvta_generic_to_shared(&Bs_h[s][0]) + (uint32_t)bk_lane * 256u;
        bbase_l[s] = (uint32_t)__cvta_generic_to_shared(&Bs_l[s][0]) + (uint32_t)bk_lane * 256u;
    }
    int bkm = bk_lane & 7;

    const __nv_bfloat16* Bh = g_wbh + woff;
    const __nv_bfloat16* Bl = g_wbl + woff;

    const float* ap0 = A + (size_t)(row0 + warp_m*32 + (lane >> 2)) * DIM + (lane & 3) * 2;
    const float* ap1 = ap0 + 16 * DIM;

    float acc[2][8][4];
    #pragma unroll
    for (int mt = 0; mt < 2; mt++)
        #pragma unroll
        for (int nt = 0; nt < 8; nt++)
            #pragma unroll
            for (int i = 0; i < 4; i++) acc[mt][nt][i] = 0.f;

    float2 af[2][4];
#define LDA(kc)                                                         \
    {                                                                   \
        int kk = (kc) * 16;                                             \
        af[0][0] = *(const float2*)(ap0 + kk);                          \
        af[0][1] = *(const float2*)(ap0 + 8*DIM + kk);                  \
        af[0][2] = *(const float2*)(ap0 + kk + 8);                      \
        af[0][3] = *(const float2*)(ap0 + 8*DIM + kk + 8);              \
        af[1][0] = *(const float2*)(ap1 + kk);                          \
        af[1][1] = *(const float2*)(ap1 + 8*DIM + kk);                  \
        af[1][2] = *(const float2*)(ap1 + kk + 8);                      \
        af[1][3] = *(const float2*)(ap1 + 8*DIM + kk + 8);              \
    }

    cp16(stBh[0], Bh + (size_t)k_b2 * ldb + col0 + n_b2);
    cp16(stBl[0], Bl + (size_t)k_b2 * ldb + col0 + n_b2);
    cp_commit();
    LDA(0);
    cp_wait0();
    __syncthreads();

    for (int kc = 0; kc < DIM/16; kc++) {
        int cur = kc & 1, nxt = cur ^ 1;
        bool has_next = (kc + 1 < DIM/16);

        if (has_next) {
            int k0 = (kc + 1) * 16;
            cp16(stBh[nxt], Bh + (size_t)(k0 + k_b2) * ldb + col0 + n_b2);
            cp16(stBl[nxt], Bl + (size_t)(k0 + k_b2) * ldb + col0 + n_b2);
            cp_commit();
        }

        uint32_t ah[2][4], al[2][4];
        #pragma unroll
        for (int mt = 0; mt < 2; mt++)
            #pragma unroll
            for (int j = 0; j < 4; j++) {
                float rx, ry;
                ah[mt][j] = pack_hi(af[mt][j].x, af[mt][j].y, rx, ry);
                al[mt][j] = pack2(rx, ry);
            }

        if (has_next) LDA(kc + 1);

        #pragma unroll
        for (int nt = 0; nt < 8; nt++) {
            uint32_t boff = (uint32_t)(((warp_n*8 + nt) ^ bkm) << 4);
            uint32_t bh2[2], bl2[2];
            ldsm_x2t(bh2, bbase_h[cur] + boff);
            ldsm_x2t(bl2, bbase_l[cur] + boff);
            mma16816(acc[0][nt], ah[0], bh2);
            mma16816(acc[1][nt], ah[1], bh2);
            mma16816(acc[0][nt], ah[0], bl2);
            mma16816(acc[1][nt], ah[1], bl2);
            mma16816(acc[0][nt], al[0], bh2);
            mma16816(acc[1][nt], al[1], bh2);
        }

        if (has_next) cp_wait0();
        __syncthreads();
    }
#undef LDA

    const float scale = 0.17677669529663687f;
    #pragma unroll
    for (int mt = 0; mt < 2; mt++) {
        int rr = row0 + warp_m*32 + mt*16 + (lane >> 2);
        int bI = rr >> 6, nI = rr & 63;
        #pragma unroll
        for (int hg = 0; hg < 2; hg++) {
            int cg = col0 + warp_n*64 + hg*32;
            float sqA = 0.f, sqB = 0.f;
            uint32_t hwA[4], lwA[4], hwB[4], lwB[4];
            #pragma unroll
            for (int j = 0; j < 4; j++) {
                int nt = hg*4 + j;
                int c = cg + j*8 + 2*(lane & 3);
                float b0 = bias[c], b1 = bias[c+1];
                float v0 = acc[mt][nt][0]+b0, v1 = acc[mt][nt][1]+b1;
                float v2 = acc[mt][nt][2]+b0, v3 = acc[mt][nt][3]+b1;
                if (mode == 0) { v0*=scale; v1*=scale; v2*=scale; v3*=scale; }
                sqA += v0*v0 + v1*v1;
                sqB += v2*v2 + v3*v3;
                float rx, ry;
                hwA[j] = pack_hi(v0, v1, rx, ry); lwA[j] = pack2(rx, ry);
                hwB[j] = pack_hi(v2, v3, rx, ry); lwB[j] = pack2(rx, ry);
            }
            sqA += __shfl_xor_sync(0xffffffffu, sqA, 1);
            sqA += __shfl_xor_sync(0xffffffffu, sqA, 2);
            sqB += __shfl_xor_sync(0xffffffffu, sqB, 1);
            sqB += __shfl_xor_sync(0xffffffffu, sqB, 2);

            uint32_t *dh, *dl;
            float* dn = nullptr;
            int hh;
            if (mode == 0)      { hh = cg >> 5;         dh = g_qh; dl = g_ql; dn = g_qn; }
            else if (cg < 256)  { hh = cg >> 5;         dh = g_kh; dl = g_kl; dn = g_kn; }
            else                { hh = (cg - 256) >> 5; dh = g_vh; dl = g_vl; }

            size_t wb = (((size_t)bI*HEADS + hh)*NTOK + nI)*16 + (lane & 3);
            #pragma unroll
            for (int j = 0; j < 4; j++) {
                dh[wb + j*4]        = hwA[j];
                dl[wb + j*4]        = lwA[j];
                dh[wb + 8*16 + j*4] = hwB[j];
                dl[wb + 8*16 + j*4] = lwB[j];
            }
            if (dn && (lane & 3) == 0) {
                size_t nb = ((size_t)bI*HEADS + hh)*NTOK + nI;
                dn[nb]     = sqrtf(sqA);
                dn[nb + 8] = sqrtf(sqB);
            }
        }
    }
}

// ============================================================
// Kernel 2b: output projection GEMM (unchanged from R11)
// ============================================================
__global__ void __launch_bounds__(256, 2) p_gemm_kernel(
    const float* __restrict__ bias, float* __restrict__ D)
{
    __shared__ alignas(16) char Bs_h[2][4096];
    __shared__ alignas(16) char Bs_l[2][4096];

    const float* A = g_ao;
    int tid = threadIdx.x;
    int lane = tid & 31, wid = tid >> 5;
    int warp_m = wid >> 1, warp_n = wid & 1;
    int row0 = blockIdx.y * 128;
    int col0 = blockIdx.x * 128;
    const int ldb = 256;

    int k_b2 = tid >> 4;
    int n_b2 = (tid & 15) * 8;
    uint32_t offB = (uint32_t)k_b2*256u + (uint32_t)(((n_b2 >> 3) ^ (k_b2 & 7)) << 4);
    uint32_t stBh[2], stBl[2];
    #pragma unroll
    for (int s = 0; s < 2; s++) {
        stBh[s] = (uint32_t)__cvta_generic_to_shared(&Bs_h[s][0]) + offB;
        stBl[s] = (uint32_t)__cvta_generic_to_shared(&Bs_l[s][0]) + offB;
    }
    int bk_lane = lane & 15;
    uint32_t bbase_h[2], bbase_l[2];
    #pragma unroll
    for (int s = 0; s < 2; s++) {
        bbase_h[s] = (uint32_t)__cvta_generic_to_shared(&Bs_h[s][0]) + (uint32_t)bk_lane * 256u;
        bbase_l[s] = (uint32_t)__cvta_generic_to_shared(&Bs_l[s][0]) + (uint32_t)bk_lane * 256u;
    }
    int bkm = bk_lane & 7;

    const __nv_bfloat16* Bh = g_wbh + 196608;
    const __nv_bfloat16* Bl = g_wbl + 196608;

    const float* ap0 = A + (size_t)(row0 + warp_m*32 + (lane >> 2)) * DIM + (lane & 3) * 2;
    const float* ap1 = ap0 + 16 * DIM;

    float acc[2][8][4];
    #pragma unroll
    for (int mt = 0; mt < 2; mt++)
        #pragma unroll
        for (int nt = 0; nt < 8; nt++)
            #pragma unroll
            for (int i = 0; i < 4; i++) acc[mt][nt][i] = 0.f;

    float2 af[2][4];
#define LDA(kc)                                                         \
    {                                                                   \
        int kk = (kc) * 16;                                             \
        af[0][0] = *(const float2*)(ap0 + kk);                          \
        af[0][1] = *(const float2*)(ap0 + 8*DIM + kk);                  \
        af[0][2] = *(const float2*)(ap0 + kk + 8);                      \
        af[0][3] = *(const float2*)(ap0 + 8*DIM + kk + 8);              \
        af[1][0] = *(const float2*)(ap1 + kk);                          \
        af[1][1] = *(const float2*)(ap1 + 8*DIM + kk);                  \
        af[1][2] = *(const float2*)(ap1 + kk + 8);                      \
        af[1][3] = *(const float2*)(ap1 + 8*DIM + kk + 8);              \
    }

    cp16(stBh[0], Bh + (size_t)k_b2 * ldb + col0 + n_b2);
    cp16(stBl[0], Bl + (size_t)k_b2 * ldb + col0 + n_b2);
    cp_commit();
    LDA(0);
    cp_wait0();
    __syncthreads();

    for (int kc = 0; kc < DIM/16; kc++) {
        int cur = kc & 1, nxt = cur ^ 1;
        bool has_next = (kc + 1 < DIM/16);

        if (has_next) {
            int k0 = (kc + 1) * 16;
            cp16(stBh[nxt], Bh + (size_t)(k0 + k_b2) * ldb + col0 + n_b2);
            cp16(stBl[nxt], Bl + (size_t)(k0 + k_b2) * ldb + col0 + n_b2);
            cp_commit();
        }

        uint32_t ah[2][4], al[2][4];
        #pragma unroll
        for (int mt = 0; mt < 2; mt++)
            #pragma unroll
            for (int j = 0; j < 4; j++) {
                float rx, ry;
                ah[mt][j] = pack_hi(af[mt][j].x, af[mt][j].y, rx, ry);
                al[mt][j] = pack2(rx, ry);
            }

        if (has_next) LDA(kc + 1);

        #pragma unroll
        for (int nt = 0; nt < 8; nt++) {
            uint32_t boff = (uint32_t)(((warp_n*8 + nt) ^ bkm) << 4);
            uint32_t bh2[2], bl2[2];
            ldsm_x2t(bh2, bbase_h[cur] + boff);
            ldsm_x2t(bl2, bbase_l[cur] + boff);
            mma16816(acc[0][nt], ah[0], bh2);
            mma16816(acc[1][nt], ah[1], bh2);
            mma16816(acc[0][nt], ah[0], bl2);
            mma16816(acc[1][nt], ah[1], bl2);
            mma16816(acc[0][nt], al[0], bh2);
            mma16816(acc[1][nt], al[1], bh2);
        }

        if (has_next) cp_wait0();
        __syncthreads();
    }
#undef LDA

    #pragma unroll
    for (int mt = 0; mt < 2; mt++) {
        int r_base = row0 + warp_m*32 + mt*16 + (lane >> 2);
        #pragma unroll
        for (int nt = 0; nt < 8; nt++) {
            int c = col0 + warp_n*64 + nt*8 + 2*(lane & 3);
            float b0 = bias[c], b1 = bias[c+1];
            *(float2*)&D[(size_t)r_base*DIM + c] =
                make_float2(acc[mt][nt][0]+b0, acc[mt][nt][1]+b1);
            *(float2*)&D[(size_t)(r_base+8)*DIM + c] =
                make_float2(acc[mt][nt][2]+b0, acc[mt][nt][3]+b1);
        }
    }
}

// ============================================================
// Kernel 3: attention — one tile/CTA, q fragments direct from gmem
// ============================================================
__global__ void __launch_bounds__(128) attn_mma_kernel(const float* __restrict__ mask)
{
    __shared__ alignas(16) char ksm[8192];
    __shared__ alignas(16) char vsm[8192];
    __shared__ float qn_s[NTOK], kn_s[NTOK];

    int b = blockIdx.x;
    int h = blockIdx.y;
    int w = b & 63;
    int tid = threadIdx.x;
    int lane = tid & 31, wid = tid >> 5;
    int mbase = wid * 16;

    uint32_t ksb = (uint32_t)__cvta_generic_to_shared(ksm);
    uint32_t vsb = (uint32_t)__cvta_generic_to_shared(vsm);

    const float* itp = g_invtau + h*4096;
    const float* bpp = g_bias   + h*4096;
    const float* mpp = mask + (size_t)w*4096;

    int r_ld = tid >> 1;
    int half = tid & 1;
    int swr = r_ld & 7;
    int ko0 = half * 2;

    size_t wb = (((size_t)b*HEADS + h)*NTOK + r_ld)*16 + half*8;
    size_t nb = ((size_t)b*HEADS + h)*NTOK;

    // ---- q fragments direct from gmem (overlaps k/v fill) ----
    uint32_t qfh[2][4], qfl[2][4];
    {
        const uint32_t* qbh = g_qh + nb*16;
        const uint32_t* qbl = g_ql + nb*16;
        int r0 = mbase + (lane >> 2);
        int wsel = lane & 3;
        #pragma unroll
        for (int kt = 0; kt < 2; kt++) {
            int w0 = kt*8 + wsel;
            qfh[kt][0] = qbh[r0*16 + w0];
            qfh[kt][1] = qbh[(r0+8)*16 + w0];
            qfh[kt][2] = qbh[r0*16 + w0 + 4];
            qfh[kt][3] = qbh[(r0+8)*16 + w0 + 4];
            qfl[kt][0] = qbl[r0*16 + w0];
            qfl[kt][1] = qbl[(r0+8)*16 + w0];
            qfl[kt][2] = qbl[r0*16 + w0 + 4];
            qfl[kt][3] = qbl[(r0+8)*16 + w0 + 4];
        }
    }

    // ---- fill k/v + norms ----
    {
        uint4 a0 = *(const uint4*)(g_kh + wb);
        uint4 a1 = *(const uint4*)(g_kh + wb + 4);
        uint4 b0 = *(const uint4*)(g_kl + wb);
        uint4 b1 = *(const uint4*)(g_kl + wb + 4);
        *(uint4*)(ksm + r_ld*128 + (((ko0+0) ^ swr) << 4))     = a0;
        *(uint4*)(ksm + r_ld*128 + (((ko0+1) ^ swr) << 4))     = a1;
        *(uint4*)(ksm + r_ld*128 + (((4+ko0+0) ^ swr) << 4))   = b0;
        *(uint4*)(ksm + r_ld*128 + (((4+ko0+1) ^ swr) << 4))   = b1;
        a0 = *(const uint4*)(g_vh + wb);
        a1 = *(const uint4*)(g_vh + wb + 4);
        b0 = *(const uint4*)(g_vl + wb);
        b1 = *(const uint4*)(g_vl + wb + 4);
        *(uint4*)(vsm + r_ld*128 + (((ko0+0) ^ swr) << 4))     = a0;
        *(uint4*)(vsm + r_ld*128 + (((ko0+1) ^ swr) << 4))     = a1;
        *(uint4*)(vsm + r_ld*128 + (((4+ko0+0) ^ swr) << 4))   = b0;
        *(uint4*)(vsm + r_ld*128 + (((4+ko0+1) ^ swr) << 4))   = b1;
        if (tid < 64) qn_s[tid] = g_qn[nb + tid];
        else          kn_s[tid - 64] = g_kn[nb + tid - 64];
    }
    __syncthreads();

    // ---- S = q k^T ----
    float sf[8][4];
    #pragma unroll
    for (int nt = 0; nt < 8; nt++)
        #pragma unroll
        for (int i = 0; i < 4; i++) sf[nt][i] = 0.f;

    #pragma unroll
    for (int kt = 0; kt < 2; kt++) {
        int krow_l = (lane & 7);
        int kko    = kt*2 + ((lane >> 3) & 1);
        uint32_t kbh[8][2], kbl[8][2];
        #pragma unroll
        for (int nt = 0; nt < 8; nt++) {
            int krow = nt*8 + krow_l;
            ldsm_x2(kbh[nt], ksb + krow*128 + ((kko ^ (krow & 7)) << 4));
            ldsm_x2(kbl[nt], ksb + krow*128 + (((4 + kko) ^ (krow & 7)) << 4));
        }
        #pragma unroll
        for (int nt = 0; nt < 8; nt++) mma16816(sf[nt], qfh[kt], kbh[nt]);
        #pragma unroll
        for (int nt = 0; nt < 8; nt++) mma16816(sf[nt], qfh[kt], kbl[nt]);
        #pragma unroll
        for (int nt = 0; nt < 8; nt++) mma16816(sf[nt], qfl[kt], kbh[nt]);
    }

    // ---- epilogue: cosine norm + tau + bias + mask ----
    int rA = mbase + (lane >> 2);
    int rB = rA + 8;
    float qnA = qn_s[rA], qnB = qn_s[rB];
    #pragma unroll
    for (int nt = 0; nt < 8; nt++) {
        int c0 = nt*8 + 2*(lane & 3);
        float2 kn2 = *(float2*)&kn_s[c0];
        int iA = rA*64 + c0, iB = rB*64 + c0;
        float2 tA = *(const float2*)(itp + iA);
        float2 tB = *(const float2*)(itp + iB);
        float2 bA = *(const float2*)(bpp + iA);
        float2 bB = *(const float2*)(bpp + iB);
        float2 mA = *(const float2*)(mpp + iA);
        float2 mB = *(const float2*)(mpp + iB);
        sf[nt][0] = __fdividef(sf[nt][0], fmaxf(qnA*kn2.x, 1e-6f)) * tA.x + bA.x + mA.x;
        sf[nt][1] = __fdividef(sf[nt][1], fmaxf(qnA*kn2.y, 1e-6f)) * tA.y + bA.y + mA.y;
        sf[nt][2] = __fdividef(sf[nt][2], fmaxf(qnB*kn2.x, 1e-6f)) * tB.x + bB.x + mB.x;
        sf[nt][3] = __fdividef(sf[nt][3], fmaxf(qnB*kn2.y, 1e-6f)) * tB.y + bB.y + mB.y;
    }

    // ---- fragment softmax ----
    {
        float mA = -1e30f, mB = -1e30f;
        #pragma unroll
        for (int nt = 0; nt < 8; nt++) {
            mA = fmaxf(mA, fmaxf(sf[nt][0], sf[nt][1]));
            mB = fmaxf(mB, fmaxf(sf[nt][2], sf[nt][3]));
        }
        mA = fmaxf(mA, __shfl_xor_sync(0xffffffffu, mA, 1));
        mA = fmaxf(mA, __shfl_xor_sync(0xffffffffu, mA, 2));
        mB = fmaxf(mB, __shfl_xor_sync(0xffffffffu, mB, 1));
        mB = fmaxf(mB, __shfl_xor_sync(0xffffffffu, mB, 2));
        float sA = 0.f, sB = 0.f;
        #pragma unroll
        for (int nt = 0; nt < 8; nt++) {
            sf[nt][0] = __expf(sf[nt][0] - mA); sA += sf[nt][0];
            sf[nt][1] = __expf(sf[nt][1] - mA); sA += sf[nt][1];
            sf[nt][2] = __expf(sf[nt][2] - mB); sB += sf[nt][2];
            sf[nt][3] = __expf(sf[nt][3] - mB); sB += sf[nt][3];
        }
        sA += __shfl_xor_sync(0xffffffffu, sA, 1);
        sA += __shfl_xor_sync(0xffffffffu, sA, 2);
        sB += __shfl_xor_sync(0xffffffffu, sB, 1);
        sB += __shfl_xor_sync(0xffffffffu, sB, 2);
        float iA2 = __fdividef(1.f, sA);
        float iB2 = __fdividef(1.f, sB);
        #pragma unroll
        for (int nt = 0; nt < 8; nt++) {
            sf[nt][0] *= iA2; sf[nt][1] *= iA2;
            sf[nt][2] *= iB2; sf[nt][3] *= iB2;
        }
    }

    // ---- O = P V ----
    float of[4][4];
    #pragma unroll
    for (int nt = 0; nt < 4; nt++)
        #pragma unroll
        for (int i = 0; i < 4; i++) of[nt][i] = 0.f;

    #pragma unroll
    for (int kt2 = 0; kt2 < 4; kt2++) {
        int ntA = 2*kt2, ntB = 2*kt2 + 1;
        uint32_t pah[4], pal[4];
        float r0, r1;
        pah[0] = pack_hi(sf[ntA][0], sf[ntA][1], r0, r1); pal[0] = pack2(r0, r1);
        pah[1] = pack_hi(sf[ntA][2], sf[ntA][3], r0, r1); pal[1] = pack2(r0, r1);
        pah[2] = pack_hi(sf[ntB][0], sf[ntB][1], r0, r1); pal[2] = pack2(r0, r1);
        pah[3] = pack_hi(sf[ntB][2], sf[ntB][3], r0, r1); pal[3] = pack2(r0, r1);
        int vrow = kt2*16 + (lane & 15);
        int vsw = vrow & 7;
        uint32_t vbh[4][2], vbl[4][2];
        #pragma unroll
        for (int nt2 = 0; nt2 < 4; nt2++) {
            ldsm_x2t(vbh[nt2], vsb + vrow*128 + ((nt2 ^ vsw) << 4));
            ldsm_x2t(vbl[nt2], vsb + vrow*128 + (((4 + nt2) ^ vsw) << 4));
        }
        #pragma unroll
        for (int nt2 = 0; nt2 < 4; nt2++) mma16816(of[nt2], pah, vbh[nt2]);
        #pragma unroll
        for (int nt2 = 0; nt2 < 4; nt2++) mma16816(of[nt2], pah, vbl[nt2]);
        #pragma unroll
        for (int nt2 = 0; nt2 < 4; nt2++) mma16816(of[nt2], pal, vbh[nt2]);
    }

    // ---- store O ----
    {
        float* ob = g_ao + ((size_t)b*NTOK)*DIM + h*HD;
        #pragma unroll
        for (int nt2 = 0; nt2 < 4; nt2++) {
            int c = nt2*8 + 2*(lane & 3);
            *(float2*)(ob + (size_t)rA*DIM + c) = make_float2(of[nt2][0], of[nt2][1]);
            *(float2*)(ob + (size_t)rB*DIM + c) = make_float2(of[nt2][2], of[nt2][3]);
        }
    }
}

// ============================================================
// launch
// ============================================================
extern "C" void kernel_launch(void* const* d_in, const int* in_sizes, int n_in,
                              void* d_out, int out_size)
{
    const float* x      = (const float*)d_in[0];
    const float* KV     = (const float*)d_in[1];
    const float* mask   = (const float*)d_in[2];
    const float* Wq     = (const float*)d_in[3];
    const float* bq     = (const float*)d_in[4];
    const float* Wkv    = (const float*)d_in[5];
    const float* bkv    = (const float*)d_in[6];
    const float* Wp     = (const float*)d_in[7];
    const float* bp     = (const float*)d_in[8];
    const float* cpb_w1 = (const float*)d_in[9];
    const float* cpb_b1 = (const float*)d_in[10];
    const float* cpb_w2 = (const float*)d_in[11];
    const float* cpb_b2 = (const float*)d_in[12];
    const float* tau    = (const float*)d_in[13];
    const float* lri    = (const float*)d_in[14];
    float* out = (float*)d_out;

    const int MT = (BWIN * NTOK) / 128;   // 1024

    prep_kernel<<<1040, 256>>>(Wq, Wkv, Wp, cpb_w1, cpb_b1, cpb_w2, cpb_b2, tau, lri);
    qkv_gemm_kernel<<<dim3(6, MT), 256>>>(x, KV, bq, bkv);
    attn_mma_kernel<<<dim3(BWIN, HEADS), 128>>>(mask);
    p_gemm_kernel<<<dim3(2, MT), 256>>>(bp, out);
}

// round 13
// speedup vs baseline: 1.2588x; 1.2588x over previous
#include <cuda_runtime.h>
#include <cuda_fp16.h>
#include <cstdint>

#define BWIN 2048
#define NTOK 64
#define DIM  256
#define HEADS 8
#define HD   32
#define NW   64

// ---- scratch (device globals; no allocations allowed) ----
__device__ uint32_t g_qh[BWIN*HEADS*NTOK*16];   // q fp16-hi packed words
__device__ uint32_t g_ql[BWIN*HEADS*NTOK*16];   // q fp16-lo (residual)
__device__ uint32_t g_kh[BWIN*HEADS*NTOK*16];   // k fp16 single
__device__ uint32_t g_vh[BWIN*HEADS*NTOK*16];   // v fp16 single
__device__ float    g_qn[BWIN*HEADS*NTOK];
__device__ float    g_kn[BWIN*HEADS*NTOK];
__device__ float g_ao[BWIN*NTOK*DIM];
__device__ float g_bias  [HEADS*NTOK*NTOK];
__device__ float g_invtau[HEADS*NTOK*NTOK];
__device__ __half g_wh[262144];                 // fp16 weights [Wq|Wkv|Wp]

// ============================================================
// helpers
// ============================================================
__device__ __forceinline__ void mma16816(float* c, const uint32_t* a, const uint32_t* b) {
    asm volatile("mma.sync.aligned.m16n8k16.row.col.f32.f16.f16.f32 "
        "{%0,%1,%2,%3}, {%4,%5,%6,%7}, {%8,%9}, {%0,%1,%2,%3};\n"
        : "+f"(c[0]), "+f"(c[1]), "+f"(c[2]), "+f"(c[3])
        : "r"(a[0]), "r"(a[1]), "r"(a[2]), "r"(a[3]), "r"(b[0]), "r"(b[1]));
}
__device__ __forceinline__ void ldsm_x2(uint32_t* r, uint32_t addr) {
    asm volatile("ldmatrix.sync.aligned.m8n8.x2.shared.b16 {%0,%1}, [%2];"
        : "=r"(r[0]), "=r"(r[1]) : "r"(addr));
}
__device__ __forceinline__ void ldsm_x2t(uint32_t* r, uint32_t addr) {
    asm volatile("ldmatrix.sync.aligned.m8n8.x2.trans.shared.b16 {%0,%1}, [%2];"
        : "=r"(r[0]), "=r"(r[1]) : "r"(addr));
}
__device__ __forceinline__ void cp16(uint32_t smem, const void* gmem) {
    asm volatile("cp.async.cg.shared.global [%0], [%1], 16;" :: "r"(smem), "l"(gmem));
}
__device__ __forceinline__ void cp_commit() { asm volatile("cp.async.commit_group;"); }
__device__ __forceinline__ void cp_wait0()  { asm volatile("cp.async.wait_group 0;"); }
__device__ __forceinline__ uint32_t pack_hi(float a, float b, float& ra, float& rb) {
    __half ha = __float2half_rn(a);
    __half hb = __float2half_rn(b);
    ra = a - __half2float(ha);
    rb = b - __half2float(hb);
    return ((uint32_t)__half_as_ushort(hb) << 16) | (uint32_t)__half_as_ushort(ha);
}
__device__ __forceinline__ uint32_t pack2(float a, float b) {
    return ((uint32_t)__half_as_ushort(__float2half_rn(b)) << 16)
         | (uint32_t)__half_as_ushort(__float2half_rn(a));
}

// ============================================================
// Kernel 0: merged weight fp16 convert + CPB bias + inv-tau
// ============================================================
__global__ void prep_kernel(const float* __restrict__ Wq,
                            const float* __restrict__ Wkv,
                            const float* __restrict__ Wp,
                            const float* __restrict__ w1, const float* __restrict__ b1,
                            const float* __restrict__ w2, const float* __restrict__ b2,
                            const float* __restrict__ tau, const float* __restrict__ lri)
{
    if (blockIdx.x < 1024) {
        int i = blockIdx.x * 256 + threadIdx.x;
        float f;
        if (i < 65536) f = Wq[i];
        else if (i < 196608) f = Wkv[i - 65536];
        else f = Wp[i - 196608];
        g_wh[i] = __float2half_rn(f);
    } else {
        int idx = (blockIdx.x - 1024) * 256 + threadIdx.x;
        if (idx >= NTOK*NTOK) return;
        float r0 = lri[idx*2 + 0];
        float r1 = lri[idx*2 + 1];
        float acc[HEADS];
        #pragma unroll
        for (int h = 0; h < HEADS; h++) acc[h] = 0.f;
        for (int k = 0; k < 256; k++) {
            float hk = fmaxf(r0 * w1[k] + r1 * w1[256 + k] + b1[k], 0.f);
            #pragma unroll
            for (int h = 0; h < HEADS; h++) acc[h] += hk * w2[k*HEADS + h];
        }
        #pragma unroll
        for (int h = 0; h < HEADS; h++) {
            g_bias[h*NTOK*NTOK + idx] = acc[h] + b2[h];
            g_invtau[h*NTOK*NTOK + idx] = 1.0f / fmaxf(tau[h*NTOK*NTOK + idx], 0.01f);
        }
    }
}

// ============================================================
// Kernel 2a: fused Q+KV projection GEMM (fp16 2-term A, 1-term B)
// ============================================================
__global__ void __launch_bounds__(256, 2) qkv_gemm_kernel(
    const float* __restrict__ Aq, const float* __restrict__ Akv,
    const float* __restrict__ bq, const float* __restrict__ bkv)
{
    __shared__ alignas(16) char Bs[2][4096];

    int bx = blockIdx.x;
    int mode = (bx < 2) ? 0 : 1;
    const float* A = (mode == 0) ? Aq : Akv;
    const float* bias = (mode == 0) ? bq : bkv;
    int ldb  = (mode == 0) ? 256 : 512;
    int woff = (mode == 0) ? 0 : 65536;
    int col0 = ((mode == 0) ? bx : bx - 2) * 128;

    int tid = threadIdx.x;
    int lane = tid & 31, wid = tid >> 5;
    int warp_m = wid >> 1, warp_n = wid & 1;
    int row0 = blockIdx.y * 128;

    int k_b2 = tid >> 4;
    int n_b2 = (tid & 15) * 8;
    uint32_t offB = (uint32_t)k_b2*256u + (uint32_t)(((n_b2 >> 3) ^ (k_b2 & 7)) << 4);
    uint32_t stB[2];
    #pragma unroll
    for (int s = 0; s < 2; s++)
        stB[s] = (uint32_t)__cvta_generic_to_shared(&Bs[s][0]) + offB;
    int bk_lane = lane & 15;
    uint32_t bbase[2];
    #pragma unroll
    for (int s = 0; s < 2; s++)
        bbase[s] = (uint32_t)__cvta_generic_to_shared(&Bs[s][0]) + (uint32_t)bk_lane * 256u;
    int bkm = bk_lane & 7;

    const __half* Bh = g_wh + woff;

    const float* ap0 = A + (size_t)(row0 + warp_m*32 + (lane >> 2)) * DIM + (lane & 3) * 2;
    const float* ap1 = ap0 + 16 * DIM;

    float acc[2][8][4];
    #pragma unroll
    for (int mt = 0; mt < 2; mt++)
        #pragma unroll
        for (int nt = 0; nt < 8; nt++)
            #pragma unroll
            for (int i = 0; i < 4; i++) acc[mt][nt][i] = 0.f;

    float2 af[2][4];
#define LDA(kc)                                                         \
    {                                                                   \
        int kk = (kc) * 16;                                             \
        af[0][0] = *(const float2*)(ap0 + kk);                          \
        af[0][1] = *(const float2*)(ap0 + 8*DIM + kk);                  \
        af[0][2] = *(const float2*)(ap0 + kk + 8);                      \
        af[0][3] = *(const float2*)(ap0 + 8*DIM + kk + 8);              \
        af[1][0] = *(const float2*)(ap1 + kk);                          \
        af[1][1] = *(const float2*)(ap1 + 8*DIM + kk);                  \
        af[1][2] = *(const float2*)(ap1 + kk + 8);                      \
        af[1][3] = *(const float2*)(ap1 + 8*DIM + kk + 8);              \
    }

    cp16(stB[0], Bh + (size_t)k_b2 * ldb + col0 + n_b2);
    cp_commit();
    LDA(0);
    cp_wait0();
    __syncthreads();

    for (int kc = 0; kc < DIM/16; kc++) {
        int cur = kc & 1, nxt = cur ^ 1;
        bool has_next = (kc + 1 < DIM/16);

        if (has_next) {
            int k0 = (kc + 1) * 16;
            cp16(stB[nxt], Bh + (size_t)(k0 + k_b2) * ldb + col0 + n_b2);
            cp_commit();
        }

        uint32_t ah[2][4], al[2][4];
        #pragma unroll
        for (int mt = 0; mt < 2; mt++)
            #pragma unroll
            for (int j = 0; j < 4; j++) {
                float rx, ry;
                ah[mt][j] = pack_hi(af[mt][j].x, af[mt][j].y, rx, ry);
                al[mt][j] = pack2(rx, ry);
            }

        if (has_next) LDA(kc + 1);

        #pragma unroll
        for (int nt = 0; nt < 8; nt++) {
            uint32_t boff = (uint32_t)(((warp_n*8 + nt) ^ bkm) << 4);
            uint32_t bh2[2];
            ldsm_x2t(bh2, bbase[cur] + boff);
            mma16816(acc[0][nt], ah[0], bh2);
            mma16816(acc[1][nt], ah[1], bh2);
            mma16816(acc[0][nt], al[0], bh2);
            mma16816(acc[1][nt], al[1], bh2);
        }

        if (has_next) cp_wait0();
        __syncthreads();
    }
#undef LDA

    const float scale = 0.17677669529663687f;
    #pragma unroll
    for (int mt = 0; mt < 2; mt++) {
        int rr = row0 + warp_m*32 + mt*16 + (lane >> 2);
        int bI = rr >> 6, nI = rr & 63;
        #pragma unroll
        for (int hg = 0; hg < 2; hg++) {
            int cg = col0 + warp_n*64 + hg*32;
            float sqA = 0.f, sqB = 0.f;
            uint32_t hwA[4], lwA[4], hwB[4], lwB[4];
            #pragma unroll
            for (int j = 0; j < 4; j++) {
                int nt = hg*4 + j;
                int c = cg + j*8 + 2*(lane & 3);
                float b0 = bias[c], b1 = bias[c+1];
                float v0 = acc[mt][nt][0]+b0, v1 = acc[mt][nt][1]+b1;
                float v2 = acc[mt][nt][2]+b0, v3 = acc[mt][nt][3]+b1;
                if (mode == 0) { v0*=scale; v1*=scale; v2*=scale; v3*=scale; }
                sqA += v0*v0 + v1*v1;
                sqB += v2*v2 + v3*v3;
                float rx, ry;
                hwA[j] = pack_hi(v0, v1, rx, ry); lwA[j] = pack2(rx, ry);
                hwB[j] = pack_hi(v2, v3, rx, ry); lwB[j] = pack2(rx, ry);
            }
            sqA += __shfl_xor_sync(0xffffffffu, sqA, 1);
            sqA += __shfl_xor_sync(0xffffffffu, sqA, 2);
            sqB += __shfl_xor_sync(0xffffffffu, sqB, 1);
            sqB += __shfl_xor_sync(0xffffffffu, sqB, 2);

            uint32_t *dh, *dl = nullptr;
            float* dn = nullptr;
            int hh;
            if (mode == 0)      { hh = cg >> 5;         dh = g_qh; dl = g_ql; dn = g_qn; }
            else if (cg < 256)  { hh = cg >> 5;         dh = g_kh; dn = g_kn; }
            else                { hh = (cg - 256) >> 5; dh = g_vh; }

            size_t wb = (((size_t)bI*HEADS + hh)*NTOK + nI)*16 + (lane & 3);
            #pragma unroll
            for (int j = 0; j < 4; j++) {
                dh[wb + j*4]        = hwA[j];
                dh[wb + 8*16 + j*4] = hwB[j];
            }
            if (dl) {
                #pragma unroll
                for (int j = 0; j < 4; j++) {
                    dl[wb + j*4]        = lwA[j];
                    dl[wb + 8*16 + j*4] = lwB[j];
                }
            }
            if (dn && (lane & 3) == 0) {
                size_t nb = ((size_t)bI*HEADS + hh)*NTOK + nI;
                dn[nb]     = sqrtf(sqA);
                dn[nb + 8] = sqrtf(sqB);
            }
        }
    }
}

// ============================================================
// Kernel 2b: output projection GEMM (fp16)
// ============================================================
__global__ void __launch_bounds__(256, 2) p_gemm_kernel(
    const float* __restrict__ bias, float* __restrict__ D)
{
    __shared__ alignas(16) char Bs[2][4096];

    const float* A = g_ao;
    int tid = threadIdx.x;
    int lane = tid & 31, wid = tid >> 5;
    int warp_m = wid >> 1, warp_n = wid & 1;
    int row0 = blockIdx.y * 128;
    int col0 = blockIdx.x * 128;
    const int ldb = 256;

    int k_b2 = tid >> 4;
    int n_b2 = (tid & 15) * 8;
    uint32_t offB = (uint32_t)k_b2*256u + (uint32_t)(((n_b2 >> 3) ^ (k_b2 & 7)) << 4);
    uint32_t stB[2];
    #pragma unroll
    for (int s = 0; s < 2; s++)
        stB[s] = (uint32_t)__cvta_generic_to_shared(&Bs[s][0]) + offB;
    int bk_lane = lane & 15;
    uint32_t bbase[2];
    #pragma unroll
    for (int s = 0; s < 2; s++)
        bbase[s] = (uint32_t)__cvta_generic_to_shared(&Bs[s][0]) + (uint32_t)bk_lane * 256u;
    int bkm = bk_lane & 7;

    const __half* Bh = g_wh + 196608;

    const float* ap0 = A + (size_t)(row0 + warp_m*32 + (lane >> 2)) * DIM + (lane & 3) * 2;
    const float* ap1 = ap0 + 16 * DIM;

    float acc[2][8][4];
    #pragma unroll
    for (int mt = 0; mt < 2; mt++)
        #pragma unroll
        for (int nt = 0; nt < 8; nt++)
            #pragma unroll
            for (int i = 0; i < 4; i++) acc[mt][nt][i] = 0.f;

    float2 af[2][4];
#define LDA(kc)                                                         \
    {                                                                   \
        int kk = (kc) * 16;                                             \
        af[0][0] = *(const float2*)(ap0 + kk);                          \
        af[0][1] = *(const float2*)(ap0 + 8*DIM + kk);                  \
        af[0][2] = *(const float2*)(ap0 + kk + 8);                      \
        af[0][3] = *(const float2*)(ap0 + 8*DIM + kk + 8);              \
        af[1][0] = *(const float2*)(ap1 + kk);                          \
        af[1][1] = *(const float2*)(ap1 + 8*DIM + kk);                  \
        af[1][2] = *(const float2*)(ap1 + kk + 8);                      \
        af[1][3] = *(const float2*)(ap1 + 8*DIM + kk + 8);              \
    }

    cp16(stB[0], Bh + (size_t)k_b2 * ldb + col0 + n_b2);
    cp_commit();
    LDA(0);
    cp_wait0();
    __syncthreads();

    for (int kc = 0; kc < DIM/16; kc++) {
        int cur = kc & 1, nxt = cur ^ 1;
        bool has_next = (kc + 1 < DIM/16);

        if (has_next) {
            int k0 = (kc + 1) * 16;
            cp16(stB[nxt], Bh + (size_t)(k0 + k_b2) * ldb + col0 + n_b2);
            cp_commit();
        }

        uint32_t ah[2][4], al[2][4];
        #pragma unroll
        for (int mt = 0; mt < 2; mt++)
            #pragma unroll
            for (int j = 0; j < 4; j++) {
                float rx, ry;
                ah[mt][j] = pack_hi(af[mt][j].x, af[mt][j].y, rx, ry);
                al[mt][j] = pack2(rx, ry);
            }

        if (has_next) LDA(kc + 1);

        #pragma unroll
        for (int nt = 0; nt < 8; nt++) {
            uint32_t boff = (uint32_t)(((warp_n*8 + nt) ^ bkm) << 4);
            uint32_t bh2[2];
            ldsm_x2t(bh2, bbase[cur] + boff);
            mma16816(acc[0][nt], ah[0], bh2);
            mma16816(acc[1][nt], ah[1], bh2);
            mma16816(acc[0][nt], al[0], bh2);
            mma16816(acc[1][nt], al[1], bh2);
        }

        if (has_next) cp_wait0();
        __syncthreads();
    }
#undef LDA

    #pragma unroll
    for (int mt = 0; mt < 2; mt++) {
        int r_base = row0 + warp_m*32 + mt*16 + (lane >> 2);
        #pragma unroll
        for (int nt = 0; nt < 8; nt++) {
            int c = col0 + warp_n*64 + nt*8 + 2*(lane & 3);
            float b0 = bias[c], b1 = bias[c+1];
            *(float2*)&D[(size_t)r_base*DIM + c] =
                make_float2(acc[mt][nt][0]+b0, acc[mt][nt][1]+b1);
            *(float2*)&D[(size_t)(r_base+8)*DIM + c] =
                make_float2(acc[mt][nt][2]+b0, acc[mt][nt][3]+b1);
        }
    }
}

// ============================================================
// Kernel 3: attention — fp16, combined k|v smem, q direct
//   kvsm row 128B: units 0-3 = k (fp16), units 4-7 = v (fp16)
// ============================================================
__global__ void __launch_bounds__(128) attn_mma_kernel(const float* __restrict__ mask)
{
    __shared__ alignas(16) char kvsm[8192];
    __shared__ float qn_s[NTOK], kn_s[NTOK];

    int b = blockIdx.x;
    int h = blockIdx.y;
    int w = b & 63;
    int tid = threadIdx.x;
    int lane = tid & 31, wid = tid >> 5;
    int mbase = wid * 16;

    uint32_t kvb = (uint32_t)__cvta_generic_to_shared(kvsm);

    const float* itp = g_invtau + h*4096;
    const float* bpp = g_bias   + h*4096;
    const float* mpp = mask + (size_t)w*4096;

    int r_ld = tid >> 1;
    int half = tid & 1;
    int swr = r_ld & 7;
    int ko0 = half * 2;

    size_t wb = (((size_t)b*HEADS + h)*NTOK + r_ld)*16 + half*8;
    size_t nb = ((size_t)b*HEADS + h)*NTOK;

    // ---- q fragments direct from gmem ----
    uint32_t qfh[2][4], qfl[2][4];
    {
        const uint32_t* qbh = g_qh + nb*16;
        const uint32_t* qbl = g_ql + nb*16;
        int r0 = mbase + (lane >> 2);
        int wsel = lane & 3;
        #pragma unroll
        for (int kt = 0; kt < 2; kt++) {
            int w0 = kt*8 + wsel;
            qfh[kt][0] = qbh[r0*16 + w0];
            qfh[kt][1] = qbh[(r0+8)*16 + w0];
            qfh[kt][2] = qbh[r0*16 + w0 + 4];
            qfh[kt][3] = qbh[(r0+8)*16 + w0 + 4];
            qfl[kt][0] = qbl[r0*16 + w0];
            qfl[kt][1] = qbl[(r0+8)*16 + w0];
            qfl[kt][2] = qbl[r0*16 + w0 + 4];
            qfl[kt][3] = qbl[(r0+8)*16 + w0 + 4];
        }
    }

    // ---- fill k (units 0-3) and v (units 4-7) + norms ----
    {
        uint4 a0 = *(const uint4*)(g_kh + wb);
        uint4 a1 = *(const uint4*)(g_kh + wb + 4);
        uint4 b0 = *(const uint4*)(g_vh + wb);
        uint4 b1 = *(const uint4*)(g_vh + wb + 4);
        *(uint4*)(kvsm + r_ld*128 + (((ko0+0) ^ swr) << 4))     = a0;
        *(uint4*)(kvsm + r_ld*128 + (((ko0+1) ^ swr) << 4))     = a1;
        *(uint4*)(kvsm + r_ld*128 + (((4+ko0+0) ^ swr) << 4))   = b0;
        *(uint4*)(kvsm + r_ld*128 + (((4+ko0+1) ^ swr) << 4))   = b1;
        if (tid < 64) qn_s[tid] = g_qn[nb + tid];
        else          kn_s[tid - 64] = g_kn[nb + tid - 64];
    }
    __syncthreads();

    // ---- S = q k^T ----
    float sf[8][4];
    #pragma unroll
    for (int nt = 0; nt < 8; nt++)
        #pragma unroll
        for (int i = 0; i < 4; i++) sf[nt][i] = 0.f;

    #pragma unroll
    for (int kt = 0; kt < 2; kt++) {
        int krow_l = (lane & 7);
        int kko    = kt*2 + ((lane >> 3) & 1);
        uint32_t kbh[8][2];
        #pragma unroll
        for (int nt = 0; nt < 8; nt++) {
            int krow = nt*8 + krow_l;
            ldsm_x2(kbh[nt], kvb + krow*128 + ((kko ^ (krow & 7)) << 4));
        }
        #pragma unroll
        for (int nt = 0; nt < 8; nt++) mma16816(sf[nt], qfh[kt], kbh[nt]);
        #pragma unroll
        for (int nt = 0; nt < 8; nt++) mma16816(sf[nt], qfl[kt], kbh[nt]);
    }

    // ---- epilogue: cosine norm + tau + bias + mask ----
    int rA = mbase + (lane >> 2);
    int rB = rA + 8;
    float qnA = qn_s[rA], qnB = qn_s[rB];
    #pragma unroll
    for (int nt = 0; nt < 8; nt++) {
        int c0 = nt*8 + 2*(lane & 3);
        float2 kn2 = *(float2*)&kn_s[c0];
        int iA = rA*64 + c0, iB = rB*64 + c0;
        float2 tA = *(const float2*)(itp + iA);
        float2 tB = *(const float2*)(itp + iB);
        float2 bA = *(const float2*)(bpp + iA);
        float2 bB = *(const float2*)(bpp + iB);
        float2 mA = *(const float2*)(mpp + iA);
        float2 mB = *(const float2*)(mpp + iB);
        sf[nt][0] = __fdividef(sf[nt][0], fmaxf(qnA*kn2.x, 1e-6f)) * tA.x + bA.x + mA.x;
        sf[nt][1] = __fdividef(sf[nt][1], fmaxf(qnA*kn2.y, 1e-6f)) * tA.y + bA.y + mA.y;
        sf[nt][2] = __fdividef(sf[nt][2], fmaxf(qnB*kn2.x, 1e-6f)) * tB.x + bB.x + mB.x;
        sf[nt][3] = __fdividef(sf[nt][3], fmaxf(qnB*kn2.y, 1e-6f)) * tB.y + bB.y + mB.y;
    }

    // ---- fragment softmax ----
    {
        float mA = -1e30f, mB = -1e30f;
        #pragma unroll
        for (int nt = 0; nt < 8; nt++) {
            mA = fmaxf(mA, fmaxf(sf[nt][0], sf[nt][1]));
            mB = fmaxf(mB, fmaxf(sf[nt][2], sf[nt][3]));
        }
        mA = fmaxf(mA, __shfl_xor_sync(0xffffffffu, mA, 1));
        mA = fmaxf(mA, __shfl_xor_sync(0xffffffffu, mA, 2));
        mB = fmaxf(mB, __shfl_xor_sync(0xffffffffu, mB, 1));
        mB = fmaxf(mB, __shfl_xor_sync(0xffffffffu, mB, 2));
        float sA = 0.f, sB = 0.f;
        #pragma unroll
        for (int nt = 0; nt < 8; nt++) {
            sf[nt][0] = __expf(sf[nt][0] - mA); sA += sf[nt][0];
            sf[nt][1] = __expf(sf[nt][1] - mA); sA += sf[nt][1];
            sf[nt][2] = __expf(sf[nt][2] - mB); sB += sf[nt][2];
            sf[nt][3] = __expf(sf[nt][3] - mB); sB += sf[nt][3];
        }
        sA += __shfl_xor_sync(0xffffffffu, sA, 1);
        sA += __shfl_xor_sync(0xffffffffu, sA, 2);
        sB += __shfl_xor_sync(0xffffffffu, sB, 1);
        sB += __shfl_xor_sync(0xffffffffu, sB, 2);
        float iA2 = __fdividef(1.f, sA);
        float iB2 = __fdividef(1.f, sB);
        #pragma unroll
        for (int nt = 0; nt < 8; nt++) {
            sf[nt][0] *= iA2; sf[nt][1] *= iA2;
            sf[nt][2] *= iB2; sf[nt][3] *= iB2;
        }
    }

    // ---- O = P V ----
    float of[4][4];
    #pragma unroll
    for (int nt = 0; nt < 4; nt++)
        #pragma unroll
        for (int i = 0; i < 4; i++) of[nt][i] = 0.f;

    #pragma unroll
    for (int kt2 = 0; kt2 < 4; kt2++) {
        int ntA = 2*kt2, ntB = 2*kt2 + 1;
        uint32_t pah[4], pal[4];
        float r0, r1;
        pah[0] = pack_hi(sf[ntA][0], sf[ntA][1], r0, r1); pal[0] = pack2(r0, r1);
        pah[1] = pack_hi(sf[ntA][2], sf[ntA][3], r0, r1); pal[1] = pack2(r0, r1);
        pah[2] = pack_hi(sf[ntB][0], sf[ntB][1], r0, r1); pal[2] = pack2(r0, r1);
        pah[3] = pack_hi(sf[ntB][2], sf[ntB][3], r0, r1); pal[3] = pack2(r0, r1);
        int vrow = kt2*16 + (lane & 15);
        int vsw = vrow & 7;
        uint32_t vbh[4][2];
        #pragma unroll
        for (int nt2 = 0; nt2 < 4; nt2++)
            ldsm_x2t(vbh[nt2], kvb + vrow*128 + (((4 + nt2) ^ vsw) << 4));
        #pragma unroll
        for (int nt2 = 0; nt2 < 4; nt2++) mma16816(of[nt2], pah, vbh[nt2]);
        #pragma unroll
        for (int nt2 = 0; nt2 < 4; nt2++) mma16816(of[nt2], pal, vbh[nt2]);
    }

    // ---- store O ----
    {
        float* ob = g_ao + ((size_t)b*NTOK)*DIM + h*HD;
        #pragma unroll
        for (int nt2 = 0; nt2 < 4; nt2++) {
            int c = nt2*8 + 2*(lane & 3);
            *(float2*)(ob + (size_t)rA*DIM + c) = make_float2(of[nt2][0], of[nt2][1]);
            *(float2*)(ob + (size_t)rB*DIM + c) = make_float2(of[nt2][2], of[nt2][3]);
        }
    }
}

// ============================================================
// launch
// ============================================================
extern "C" void kernel_launch(void* const* d_in, const int* in_sizes, int n_in,
                              void* d_out, int out_size)
{
    const float* x      = (const float*)d_in[0];
    const float* KV     = (const float*)d_in[1];
    const float* mask   = (const float*)d_in[2];
    const float* Wq     = (const float*)d_in[3];
    const float* bq     = (const float*)d_in[4];
    const float* Wkv    = (const float*)d_in[5];
    const float* bkv    = (const float*)d_in[6];
    const float* Wp     = (const float*)d_in[7];
    const float* bp     = (const float*)d_in[8];
    const float* cpb_w1 = (const float*)d_in[9];
    const float* cpb_b1 = (const float*)d_in[10];
    const float* cpb_w2 = (const float*)d_in[11];
    const float* cpb_b2 = (const float*)d_in[12];
    const float* tau    = (const float*)d_in[13];
    const float* lri    = (const float*)d_in[14];
    float* out = (float*)d_out;

    const int MT = (BWIN * NTOK) / 128;   // 1024

    prep_kernel<<<1040, 256>>>(Wq, Wkv, Wp, cpb_w1, cpb_b1, cpb_w2, cpb_b2, tau, lri);
    qkv_gemm_kernel<<<dim3(6, MT), 256>>>(x, KV, bq, bkv);
    attn_mma_kernel<<<dim3(BWIN, HEADS), 128>>>(mask);
    p_gemm_kernel<<<dim3(2, MT), 256>>>(bp, out);
}

// round 14
// speedup vs baseline: 1.3337x; 1.0595x over previous
#include <cuda_runtime.h>
#include <cuda_fp16.h>
#include <cstdint>

#define BWIN 2048
#define NTOK 64
#define DIM  256
#define HEADS 8
#define HD   32
#define NW   64

// ---- scratch (device globals; no allocations allowed) ----
__device__ uint32_t g_qh[BWIN*HEADS*NTOK*16];   // q fp16 packed words
__device__ uint32_t g_kh[BWIN*HEADS*NTOK*16];   // k fp16
__device__ uint32_t g_vh[BWIN*HEADS*NTOK*16];   // v fp16
__device__ float    g_qn[BWIN*HEADS*NTOK];
__device__ float    g_kn[BWIN*HEADS*NTOK];
__device__ float g_ao[BWIN*NTOK*DIM];
__device__ float g_bias  [HEADS*NTOK*NTOK];
__device__ float g_invtau[HEADS*NTOK*NTOK];
__device__ __half g_wh[262144];                 // fp16 weights [Wq|Wkv|Wp]

// ============================================================
// helpers
// ============================================================
__device__ __forceinline__ void mma16816(float* c, const uint32_t* a, const uint32_t* b) {
    asm volatile("mma.sync.aligned.m16n8k16.row.col.f32.f16.f16.f32 "
        "{%0,%1,%2,%3}, {%4,%5,%6,%7}, {%8,%9}, {%0,%1,%2,%3};\n"
        : "+f"(c[0]), "+f"(c[1]), "+f"(c[2]), "+f"(c[3])
        : "r"(a[0]), "r"(a[1]), "r"(a[2]), "r"(a[3]), "r"(b[0]), "r"(b[1]));
}
__device__ __forceinline__ void ldsm_x2(uint32_t* r, uint32_t addr) {
    asm volatile("ldmatrix.sync.aligned.m8n8.x2.shared.b16 {%0,%1}, [%2];"
        : "=r"(r[0]), "=r"(r[1]) : "r"(addr));
}
__device__ __forceinline__ void ldsm_x2t(uint32_t* r, uint32_t addr) {
    asm volatile("ldmatrix.sync.aligned.m8n8.x2.trans.shared.b16 {%0,%1}, [%2];"
        : "=r"(r[0]), "=r"(r[1]) : "r"(addr));
}
__device__ __forceinline__ void cp16(uint32_t smem, const void* gmem) {
    asm volatile("cp.async.cg.shared.global [%0], [%1], 16;" :: "r"(smem), "l"(gmem));
}
__device__ __forceinline__ void cp_commit() { asm volatile("cp.async.commit_group;"); }
__device__ __forceinline__ void cp_wait0()  { asm volatile("cp.async.wait_group 0;"); }
__device__ __forceinline__ uint32_t pack_hi(float a, float b, float& ra, float& rb) {
    __half ha = __float2half_rn(a);
    __half hb = __float2half_rn(b);
    ra = a - __half2float(ha);
    rb = b - __half2float(hb);
    return ((uint32_t)__half_as_ushort(hb) << 16) | (uint32_t)__half_as_ushort(ha);
}
__device__ __forceinline__ uint32_t pack2(float a, float b) {
    return ((uint32_t)__half_as_ushort(__float2half_rn(b)) << 16)
         | (uint32_t)__half_as_ushort(__float2half_rn(a));
}

// ============================================================
// Kernel 0: merged weight fp16 convert + CPB bias + inv-tau
// ============================================================
__global__ void prep_kernel(const float* __restrict__ Wq,
                            const float* __restrict__ Wkv,
                            const float* __restrict__ Wp,
                            const float* __restrict__ w1, const float* __restrict__ b1,
                            const float* __restrict__ w2, const float* __restrict__ b2,
                            const float* __restrict__ tau, const float* __restrict__ lri)
{
    if (blockIdx.x < 1024) {
        int i = blockIdx.x * 256 + threadIdx.x;
        float f;
        if (i < 65536) f = Wq[i];
        else if (i < 196608) f = Wkv[i - 65536];
        else f = Wp[i - 196608];
        g_wh[i] = __float2half_rn(f);
    } else {
        int idx = (blockIdx.x - 1024) * 256 + threadIdx.x;
        if (idx >= NTOK*NTOK) return;
        float r0 = lri[idx*2 + 0];
        float r1 = lri[idx*2 + 1];
        float acc[HEADS];
        #pragma unroll
        for (int h = 0; h < HEADS; h++) acc[h] = 0.f;
        for (int k = 0; k < 256; k++) {
            float hk = fmaxf(r0 * w1[k] + r1 * w1[256 + k] + b1[k], 0.f);
            #pragma unroll
            for (int h = 0; h < HEADS; h++) acc[h] += hk * w2[k*HEADS + h];
        }
        #pragma unroll
        for (int h = 0; h < HEADS; h++) {
            g_bias[h*NTOK*NTOK + idx] = acc[h] + b2[h];
            g_invtau[h*NTOK*NTOK + idx] = 1.0f / fmaxf(tau[h*NTOK*NTOK + idx], 0.01f);
        }
    }
}

// ============================================================
// Kernel 2a: fused Q+KV projection GEMM (fp16 single A, single B)
// ============================================================
__global__ void __launch_bounds__(256, 2) qkv_gemm_kernel(
    const float* __restrict__ Aq, const float* __restrict__ Akv,
    const float* __restrict__ bq, const float* __restrict__ bkv)
{
    __shared__ alignas(16) char Bs[2][4096];

    int bx = blockIdx.x;
    int mode = (bx < 2) ? 0 : 1;
    const float* A = (mode == 0) ? Aq : Akv;
    const float* bias = (mode == 0) ? bq : bkv;
    int ldb  = (mode == 0) ? 256 : 512;
    int woff = (mode == 0) ? 0 : 65536;
    int col0 = ((mode == 0) ? bx : bx - 2) * 128;

    int tid = threadIdx.x;
    int lane = tid & 31, wid = tid >> 5;
    int warp_m = wid >> 1, warp_n = wid & 1;
    int row0 = blockIdx.y * 128;

    int k_b2 = tid >> 4;
    int n_b2 = (tid & 15) * 8;
    uint32_t offB = (uint32_t)k_b2*256u + (uint32_t)(((n_b2 >> 3) ^ (k_b2 & 7)) << 4);
    uint32_t stB[2];
    #pragma unroll
    for (int s = 0; s < 2; s++)
        stB[s] = (uint32_t)__cvta_generic_to_shared(&Bs[s][0]) + offB;
    int bk_lane = lane & 15;
    uint32_t bbase[2];
    #pragma unroll
    for (int s = 0; s < 2; s++)
        bbase[s] = (uint32_t)__cvta_generic_to_shared(&Bs[s][0]) + (uint32_t)bk_lane * 256u;
    int bkm = bk_lane & 7;

    const __half* Bh = g_wh + woff;

    const float* ap0 = A + (size_t)(row0 + warp_m*32 + (lane >> 2)) * DIM + (lane & 3) * 2;
    const float* ap1 = ap0 + 16 * DIM;

    float acc[2][8][4];
    #pragma unroll
    for (int mt = 0; mt < 2; mt++)
        #pragma unroll
        for (int nt = 0; nt < 8; nt++)
            #pragma unroll
            for (int i = 0; i < 4; i++) acc[mt][nt][i] = 0.f;

    float2 af[2][4];
#define LDA(kc)                                                         \
    {                                                                   \
        int kk = (kc) * 16;                                             \
        af[0][0] = *(const float2*)(ap0 + kk);                          \
        af[0][1] = *(const float2*)(ap0 + 8*DIM + kk);                  \
        af[0][2] = *(const float2*)(ap0 + kk + 8);                      \
        af[0][3] = *(const float2*)(ap0 + 8*DIM + kk + 8);              \
        af[1][0] = *(const float2*)(ap1 + kk);                          \
        af[1][1] = *(const float2*)(ap1 + 8*DIM + kk);                  \
        af[1][2] = *(const float2*)(ap1 + kk + 8);                      \
        af[1][3] = *(const float2*)(ap1 + 8*DIM + kk + 8);              \
    }

    cp16(stB[0], Bh + (size_t)k_b2 * ldb + col0 + n_b2);
    cp_commit();
    LDA(0);
    cp_wait0();
    __syncthreads();

    for (int kc = 0; kc < DIM/16; kc++) {
        int cur = kc & 1, nxt = cur ^ 1;
        bool has_next = (kc + 1 < DIM/16);

        if (has_next) {
            int k0 = (kc + 1) * 16;
            cp16(stB[nxt], Bh + (size_t)(k0 + k_b2) * ldb + col0 + n_b2);
            cp_commit();
        }

        uint32_t ah[2][4];
        #pragma unroll
        for (int mt = 0; mt < 2; mt++)
            #pragma unroll
            for (int j = 0; j < 4; j++)
                ah[mt][j] = pack2(af[mt][j].x, af[mt][j].y);

        if (has_next) LDA(kc + 1);

        #pragma unroll
        for (int nt = 0; nt < 8; nt++) {
            uint32_t boff = (uint32_t)(((warp_n*8 + nt) ^ bkm) << 4);
            uint32_t bh2[2];
            ldsm_x2t(bh2, bbase[cur] + boff);
            mma16816(acc[0][nt], ah[0], bh2);
            mma16816(acc[1][nt], ah[1], bh2);
        }

        if (has_next) cp_wait0();
        __syncthreads();
    }
#undef LDA

    const float scale = 0.17677669529663687f;
    #pragma unroll
    for (int mt = 0; mt < 2; mt++) {
        int rr = row0 + warp_m*32 + mt*16 + (lane >> 2);
        int bI = rr >> 6, nI = rr & 63;
        #pragma unroll
        for (int hg = 0; hg < 2; hg++) {
            int cg = col0 + warp_n*64 + hg*32;
            float sqA = 0.f, sqB = 0.f;
            uint32_t hwA[4], hwB[4];
            #pragma unroll
            for (int j = 0; j < 4; j++) {
                int nt = hg*4 + j;
                int c = cg + j*8 + 2*(lane & 3);
                float b0 = bias[c], b1 = bias[c+1];
                float v0 = acc[mt][nt][0]+b0, v1 = acc[mt][nt][1]+b1;
                float v2 = acc[mt][nt][2]+b0, v3 = acc[mt][nt][3]+b1;
                if (mode == 0) { v0*=scale; v1*=scale; v2*=scale; v3*=scale; }
                sqA += v0*v0 + v1*v1;
                sqB += v2*v2 + v3*v3;
                hwA[j] = pack2(v0, v1);
                hwB[j] = pack2(v2, v3);
            }
            sqA += __shfl_xor_sync(0xffffffffu, sqA, 1);
            sqA += __shfl_xor_sync(0xffffffffu, sqA, 2);
            sqB += __shfl_xor_sync(0xffffffffu, sqB, 1);
            sqB += __shfl_xor_sync(0xffffffffu, sqB, 2);

            uint32_t *dh;
            float* dn = nullptr;
            int hh;
            if (mode == 0)      { hh = cg >> 5;         dh = g_qh; dn = g_qn; }
            else if (cg < 256)  { hh = cg >> 5;         dh = g_kh; dn = g_kn; }
            else                { hh = (cg - 256) >> 5; dh = g_vh; }

            size_t wb = (((size_t)bI*HEADS + hh)*NTOK + nI)*16 + (lane & 3);
            #pragma unroll
            for (int j = 0; j < 4; j++) {
                dh[wb + j*4]        = hwA[j];
                dh[wb + 8*16 + j*4] = hwB[j];
            }
            if (dn && (lane & 3) == 0) {
                size_t nb = ((size_t)bI*HEADS + hh)*NTOK + nI;
                dn[nb]     = sqrtf(sqA);
                dn[nb + 8] = sqrtf(sqB);
            }
        }
    }
}

// ============================================================
// Kernel 2b: output projection GEMM (fp16 B, 2-term A — final output)
// ============================================================
__global__ void __launch_bounds__(256, 2) p_gemm_kernel(
    const float* __restrict__ bias, float* __restrict__ D)
{
    __shared__ alignas(16) char Bs[2][4096];

    const float* A = g_ao;
    int tid = threadIdx.x;
    int lane = tid & 31, wid = tid >> 5;
    int warp_m = wid >> 1, warp_n = wid & 1;
    int row0 = blockIdx.y * 128;
    int col0 = blockIdx.x * 128;
    const int ldb = 256;

    int k_b2 = tid >> 4;
    int n_b2 = (tid & 15) * 8;
    uint32_t offB = (uint32_t)k_b2*256u + (uint32_t)(((n_b2 >> 3) ^ (k_b2 & 7)) << 4);
    uint32_t stB[2];
    #pragma unroll
    for (int s = 0; s < 2; s++)
        stB[s] = (uint32_t)__cvta_generic_to_shared(&Bs[s][0]) + offB;
    int bk_lane = lane & 15;
    uint32_t bbase[2];
    #pragma unroll
    for (int s = 0; s < 2; s++)
        bbase[s] = (uint32_t)__cvta_generic_to_shared(&Bs[s][0]) + (uint32_t)bk_lane * 256u;
    int bkm = bk_lane & 7;

    const __half* Bh = g_wh + 196608;

    const float* ap0 = A + (size_t)(row0 + warp_m*32 + (lane >> 2)) * DIM + (lane & 3) * 2;
    const float* ap1 = ap0 + 16 * DIM;

    float acc[2][8][4];
    #pragma unroll
    for (int mt = 0; mt < 2; mt++)
        #pragma unroll
        for (int nt = 0; nt < 8; nt++)
            #pragma unroll
            for (int i = 0; i < 4; i++) acc[mt][nt][i] = 0.f;

    float2 af[2][4];
#define LDA(kc)                                                         \
    {                                                                   \
        int kk = (kc) * 16;                                             \
        af[0][0] = *(const float2*)(ap0 + kk);                          \
        af[0][1] = *(const float2*)(ap0 + 8*DIM + kk);                  \
        af[0][2] = *(const float2*)(ap0 + kk + 8);                      \
        af[0][3] = *(const float2*)(ap0 + 8*DIM + kk + 8);              \
        af[1][0] = *(const float2*)(ap1 + kk);                          \
        af[1][1] = *(const float2*)(ap1 + 8*DIM + kk);                  \
        af[1][2] = *(const float2*)(ap1 + kk + 8);                      \
        af[1][3] = *(const float2*)(ap1 + 8*DIM + kk + 8);              \
    }

    cp16(stB[0], Bh + (size_t)k_b2 * ldb + col0 + n_b2);
    cp_commit();
    LDA(0);
    cp_wait0();
    __syncthreads();

    for (int kc = 0; kc < DIM/16; kc++) {
        int cur = kc & 1, nxt = cur ^ 1;
        bool has_next = (kc + 1 < DIM/16);

        if (has_next) {
            int k0 = (kc + 1) * 16;
            cp16(stB[nxt], Bh + (size_t)(k0 + k_b2) * ldb + col0 + n_b2);
            cp_commit();
        }

        uint32_t ah[2][4], al[2][4];
        #pragma unroll
        for (int mt = 0; mt < 2; mt++)
            #pragma unroll
            for (int j = 0; j < 4; j++) {
                float rx, ry;
                ah[mt][j] = pack_hi(af[mt][j].x, af[mt][j].y, rx, ry);
                al[mt][j] = pack2(rx, ry);
            }

        if (has_next) LDA(kc + 1);

        #pragma unroll
        for (int nt = 0; nt < 8; nt++) {
            uint32_t boff = (uint32_t)(((warp_n*8 + nt) ^ bkm) << 4);
            uint32_t bh2[2];
            ldsm_x2t(bh2, bbase[cur] + boff);
            mma16816(acc[0][nt], ah[0], bh2);
            mma16816(acc[1][nt], ah[1], bh2);
            mma16816(acc[0][nt], al[0], bh2);
            mma16816(acc[1][nt], al[1], bh2);
        }

        if (has_next) cp_wait0();
        __syncthreads();
    }
#undef LDA

    #pragma unroll
    for (int mt = 0; mt < 2; mt++) {
        int r_base = row0 + warp_m*32 + mt*16 + (lane >> 2);
        #pragma unroll
        for (int nt = 0; nt < 8; nt++) {
            int c = col0 + warp_n*64 + nt*8 + 2*(lane & 3);
            float b0 = bias[c], b1 = bias[c+1];
            *(float2*)&D[(size_t)r_base*DIM + c] =
                make_float2(acc[mt][nt][0]+b0, acc[mt][nt][1]+b1);
            *(float2*)&D[(size_t)(r_base+8)*DIM + c] =
                make_float2(acc[mt][nt][2]+b0, acc[mt][nt][3]+b1);
        }
    }
}

// ============================================================
// Kernel 3: attention — fp16 single-term q/k/v/P, combined k|v smem
// ============================================================
__global__ void __launch_bounds__(128) attn_mma_kernel(const float* __restrict__ mask)
{
    __shared__ alignas(16) char kvsm[8192];
    __shared__ float qn_s[NTOK], kn_s[NTOK];

    int b = blockIdx.x;
    int h = blockIdx.y;
    int w = b & 63;
    int tid = threadIdx.x;
    int lane = tid & 31, wid = tid >> 5;
    int mbase = wid * 16;

    uint32_t kvb = (uint32_t)__cvta_generic_to_shared(kvsm);

    const float* itp = g_invtau + h*4096;
    const float* bpp = g_bias   + h*4096;
    const float* mpp = mask + (size_t)w*4096;

    int r_ld = tid >> 1;
    int half = tid & 1;
    int swr = r_ld & 7;
    int ko0 = half * 2;

    size_t wb = (((size_t)b*HEADS + h)*NTOK + r_ld)*16 + half*8;
    size_t nb = ((size_t)b*HEADS + h)*NTOK;

    // ---- q fragments direct from gmem ----
    uint32_t qfh[2][4];
    {
        const uint32_t* qbh = g_qh + nb*16;
        int r0 = mbase + (lane >> 2);
        int wsel = lane & 3;
        #pragma unroll
        for (int kt = 0; kt < 2; kt++) {
            int w0 = kt*8 + wsel;
            qfh[kt][0] = qbh[r0*16 + w0];
            qfh[kt][1] = qbh[(r0+8)*16 + w0];
            qfh[kt][2] = qbh[r0*16 + w0 + 4];
            qfh[kt][3] = qbh[(r0+8)*16 + w0 + 4];
        }
    }

    // ---- fill k (units 0-3) and v (units 4-7) + norms ----
    {
        uint4 a0 = *(const uint4*)(g_kh + wb);
        uint4 a1 = *(const uint4*)(g_kh + wb + 4);
        uint4 b0 = *(const uint4*)(g_vh + wb);
        uint4 b1 = *(const uint4*)(g_vh + wb + 4);
        *(uint4*)(kvsm + r_ld*128 + (((ko0+0) ^ swr) << 4))     = a0;
        *(uint4*)(kvsm + r_ld*128 + (((ko0+1) ^ swr) << 4))     = a1;
        *(uint4*)(kvsm + r_ld*128 + (((4+ko0+0) ^ swr) << 4))   = b0;
        *(uint4*)(kvsm + r_ld*128 + (((4+ko0+1) ^ swr) << 4))   = b1;
        if (tid < 64) qn_s[tid] = g_qn[nb + tid];
        else          kn_s[tid - 64] = g_kn[nb + tid - 64];
    }
    __syncthreads();

    // ---- S = q k^T ----
    float sf[8][4];
    #pragma unroll
    for (int nt = 0; nt < 8; nt++)
        #pragma unroll
        for (int i = 0; i < 4; i++) sf[nt][i] = 0.f;

    #pragma unroll
    for (int kt = 0; kt < 2; kt++) {
        int krow_l = (lane & 7);
        int kko    = kt*2 + ((lane >> 3) & 1);
        uint32_t kbh[8][2];
        #pragma unroll
        for (int nt = 0; nt < 8; nt++) {
            int krow = nt*8 + krow_l;
            ldsm_x2(kbh[nt], kvb + krow*128 + ((kko ^ (krow & 7)) << 4));
        }
        #pragma unroll
        for (int nt = 0; nt < 8; nt++) mma16816(sf[nt], qfh[kt], kbh[nt]);
    }

    // ---- epilogue: cosine norm + tau + bias + mask ----
    int rA = mbase + (lane >> 2);
    int rB = rA + 8;
    float qnA = qn_s[rA], qnB = qn_s[rB];
    #pragma unroll
    for (int nt = 0; nt < 8; nt++) {
        int c0 = nt*8 + 2*(lane & 3);
        float2 kn2 = *(float2*)&kn_s[c0];
        int iA = rA*64 + c0, iB = rB*64 + c0;
        float2 tA = *(const float2*)(itp + iA);
        float2 tB = *(const float2*)(itp + iB);
        float2 bA = *(const float2*)(bpp + iA);
        float2 bB = *(const float2*)(bpp + iB);
        float2 mA = *(const float2*)(mpp + iA);
        float2 mB = *(const float2*)(mpp + iB);
        sf[nt][0] = __fdividef(sf[nt][0], fmaxf(qnA*kn2.x, 1e-6f)) * tA.x + bA.x + mA.x;
        sf[nt][1] = __fdividef(sf[nt][1], fmaxf(qnA*kn2.y, 1e-6f)) * tA.y + bA.y + mA.y;
        sf[nt][2] = __fdividef(sf[nt][2], fmaxf(qnB*kn2.x, 1e-6f)) * tB.x + bB.x + mB.x;
        sf[nt][3] = __fdividef(sf[nt][3], fmaxf(qnB*kn2.y, 1e-6f)) * tB.y + bB.y + mB.y;
    }

    // ---- fragment softmax ----
    {
        float mA = -1e30f, mB = -1e30f;
        #pragma unroll
        for (int nt = 0; nt < 8; nt++) {
            mA = fmaxf(mA, fmaxf(sf[nt][0], sf[nt][1]));
            mB = fmaxf(mB, fmaxf(sf[nt][2], sf[nt][3]));
        }
        mA = fmaxf(mA, __shfl_xor_sync(0xffffffffu, mA, 1));
        mA = fmaxf(mA, __shfl_xor_sync(0xffffffffu, mA, 2));
        mB = fmaxf(mB, __shfl_xor_sync(0xffffffffu, mB, 1));
        mB = fmaxf(mB, __shfl_xor_sync(0xffffffffu, mB, 2));
        float sA = 0.f, sB = 0.f;
        #pragma unroll
        for (int nt = 0; nt < 8; nt++) {
            sf[nt][0] = __expf(sf[nt][0] - mA); sA += sf[nt][0];
            sf[nt][1] = __expf(sf[nt][1] - mA); sA += sf[nt][1];
            sf[nt][2] = __expf(sf[nt][2] - mB); sB += sf[nt][2];
            sf[nt][3] = __expf(sf[nt][3] - mB); sB += sf[nt][3];
        }
        sA += __shfl_xor_sync(0xffffffffu, sA, 1);
        sA += __shfl_xor_sync(0xffffffffu, sA, 2);
        sB += __shfl_xor_sync(0xffffffffu, sB, 1);
        sB += __shfl_xor_sync(0xffffffffu, sB, 2);
        float iA2 = __fdividef(1.f, sA);
        float iB2 = __fdividef(1.f, sB);
        #pragma unroll
        for (int nt = 0; nt < 8; nt++) {
            sf[nt][0] *= iA2; sf[nt][1] *= iA2;
            sf[nt][2] *= iB2; sf[nt][3] *= iB2;
        }
    }

    // ---- O = P V (P single fp16) ----
    float of[4][4];
    #pragma unroll
    for (int nt = 0; nt < 4; nt++)
        #pragma unroll
        for (int i = 0; i < 4; i++) of[nt][i] = 0.f;

    #pragma unroll
    for (int kt2 = 0; kt2 < 4; kt2++) {
        int ntA = 2*kt2, ntB = 2*kt2 + 1;
        uint32_t pah[4];
        pah[0] = pack2(sf[ntA][0], sf[ntA][1]);
        pah[1] = pack2(sf[ntA][2], sf[ntA][3]);
        pah[2] = pack2(sf[ntB][0], sf[ntB][1]);
        pah[3] = pack2(sf[ntB][2], sf[ntB][3]);
        int vrow = kt2*16 + (lane & 15);
        int vsw = vrow & 7;
        uint32_t vbh[4][2];
        #pragma unroll
        for (int nt2 = 0; nt2 < 4; nt2++)
            ldsm_x2t(vbh[nt2], kvb + vrow*128 + (((4 + nt2) ^ vsw) << 4));
        #pragma unroll
        for (int nt2 = 0; nt2 < 4; nt2++) mma16816(of[nt2], pah, vbh[nt2]);
    }

    // ---- store O ----
    {
        float* ob = g_ao + ((size_t)b*NTOK)*DIM + h*HD;
        #pragma unroll
        for (int nt2 = 0; nt2 < 4; nt2++) {
            int c = nt2*8 + 2*(lane & 3);
            *(float2*)(ob + (size_t)rA*DIM + c) = make_float2(of[nt2][0], of[nt2][1]);
            *(float2*)(ob + (size_t)rB*DIM + c) = make_float2(of[nt2][2], of[nt2][3]);
        }
    }
}

// ============================================================
// launch
// ============================================================
extern "C" void kernel_launch(void* const* d_in, const int* in_sizes, int n_in,
                              void* d_out, int out_size)
{
    const float* x      = (const float*)d_in[0];
    const float* KV     = (const float*)d_in[1];
    const float* mask   = (const float*)d_in[2];
    const float* Wq     = (const float*)d_in[3];
    const float* bq     = (const float*)d_in[4];
    const float* Wkv    = (const float*)d_in[5];
    const float* bkv    = (const float*)d_in[6];
    const float* Wp     = (const float*)d_in[7];
    const float* bp     = (const float*)d_in[8];
    const float* cpb_w1 = (const float*)d_in[9];
    const float* cpb_b1 = (const float*)d_in[10];
    const float* cpb_w2 = (const float*)d_in[11];
    const float* cpb_b2 = (const float*)d_in[12];
    const float* tau    = (const float*)d_in[13];
    const float* lri    = (const float*)d_in[14];
    float* out = (float*)d_out;

    const int MT = (BWIN * NTOK) / 128;   // 1024

    prep_kernel<<<1040, 256>>>(Wq, Wkv, Wp, cpb_w1, cpb_b1, cpb_w2, cpb_b2, tau, lri);
    qkv_gemm_kernel<<<dim3(6, MT), 256>>>(x, KV, bq, bkv);
    attn_mma_kernel<<<dim3(BWIN, HEADS), 128>>>(mask);
    p_gemm_kernel<<<dim3(2, MT), 256>>>(bp, out);
}

// round 15
// speedup vs baseline: 1.4558x; 1.0915x over previous
#include <cuda_runtime.h>
#include <cuda_fp16.h>
#include <cstdint>

#define BWIN 2048
#define NTOK 64
#define DIM  256
#define HEADS 8
#define HD   32
#define NW   64

// ---- scratch (device globals; no allocations allowed) ----
__device__ uint32_t g_qh[BWIN*HEADS*NTOK*16];   // q fp16 packed words
__device__ uint32_t g_kh[BWIN*HEADS*NTOK*16];   // k fp16
__device__ uint32_t g_vh[BWIN*HEADS*NTOK*16];   // v fp16
__device__ float    g_qn[BWIN*HEADS*NTOK];
__device__ float    g_kn[BWIN*HEADS*NTOK];
__device__ uint32_t g_aoh[BWIN*NTOK*128];       // attention out, fp16 packed (256 halves/row)
__device__ float g_bias  [HEADS*NTOK*NTOK];
__device__ float g_invtau[HEADS*NTOK*NTOK];
__device__ __half g_wh[262144];                 // fp16 weights [Wq|Wkv|Wp]

// ============================================================
// helpers
// ============================================================
__device__ __forceinline__ void mma16816(float* c, const uint32_t* a, const uint32_t* b) {
    asm volatile("mma.sync.aligned.m16n8k16.row.col.f32.f16.f16.f32 "
        "{%0,%1,%2,%3}, {%4,%5,%6,%7}, {%8,%9}, {%0,%1,%2,%3};\n"
        : "+f"(c[0]), "+f"(c[1]), "+f"(c[2]), "+f"(c[3])
        : "r"(a[0]), "r"(a[1]), "r"(a[2]), "r"(a[3]), "r"(b[0]), "r"(b[1]));
}
__device__ __forceinline__ void ldsm_x4(uint32_t* r, uint32_t addr) {
    asm volatile("ldmatrix.sync.aligned.m8n8.x4.shared.b16 {%0,%1,%2,%3}, [%4];"
        : "=r"(r[0]), "=r"(r[1]), "=r"(r[2]), "=r"(r[3]) : "r"(addr));
}
__device__ __forceinline__ void ldsm_x2(uint32_t* r, uint32_t addr) {
    asm volatile("ldmatrix.sync.aligned.m8n8.x2.shared.b16 {%0,%1}, [%2];"
        : "=r"(r[0]), "=r"(r[1]) : "r"(addr));
}
__device__ __forceinline__ void ldsm_x2t(uint32_t* r, uint32_t addr) {
    asm volatile("ldmatrix.sync.aligned.m8n8.x2.trans.shared.b16 {%0,%1}, [%2];"
        : "=r"(r[0]), "=r"(r[1]) : "r"(addr));
}
__device__ __forceinline__ void cp16(uint32_t smem, const void* gmem) {
    asm volatile("cp.async.cg.shared.global [%0], [%1], 16;" :: "r"(smem), "l"(gmem));
}
__device__ __forceinline__ void cp_commit() { asm volatile("cp.async.commit_group;"); }
__device__ __forceinline__ void cp_wait0()  { asm volatile("cp.async.wait_group 0;"); }
__device__ __forceinline__ uint32_t pack2(float a, float b) {
    return ((uint32_t)__half_as_ushort(__float2half_rn(b)) << 16)
         | (uint32_t)__half_as_ushort(__float2half_rn(a));
}

// ============================================================
// Kernel 0: merged weight fp16 convert + CPB bias + inv-tau
// ============================================================
__global__ void prep_kernel(const float* __restrict__ Wq,
                            const float* __restrict__ Wkv,
                            const float* __restrict__ Wp,
                            const float* __restrict__ w1, const float* __restrict__ b1,
                            const float* __restrict__ w2, const float* __restrict__ b2,
                            const float* __restrict__ tau, const float* __restrict__ lri)
{
    if (blockIdx.x < 1024) {
        int i = blockIdx.x * 256 + threadIdx.x;
        float f;
        if (i < 65536) f = Wq[i];
        else if (i < 196608) f = Wkv[i - 65536];
        else f = Wp[i - 196608];
        g_wh[i] = __float2half_rn(f);
    } else {
        int idx = (blockIdx.x - 1024) * 256 + threadIdx.x;
        if (idx >= NTOK*NTOK) return;
        float r0 = lri[idx*2 + 0];
        float r1 = lri[idx*2 + 1];
        float acc[HEADS];
        #pragma unroll
        for (int h = 0; h < HEADS; h++) acc[h] = 0.f;
        for (int k = 0; k < 256; k++) {
            float hk = fmaxf(r0 * w1[k] + r1 * w1[256 + k] + b1[k], 0.f);
            #pragma unroll
            for (int h = 0; h < HEADS; h++) acc[h] += hk * w2[k*HEADS + h];
        }
        #pragma unroll
        for (int h = 0; h < HEADS; h++) {
            g_bias[h*NTOK*NTOK + idx] = acc[h] + b2[h];
            g_invtau[h*NTOK*NTOK + idx] = 1.0f / fmaxf(tau[h*NTOK*NTOK + idx], 0.01f);
        }
    }
}

// ============================================================
// Kernel 2a: fused Q+KV projection GEMM (fp16 single A, single B)
// ============================================================
__global__ void __launch_bounds__(256, 2) qkv_gemm_kernel(
    const float* __restrict__ Aq, const float* __restrict__ Akv,
    const float* __restrict__ bq, const float* __restrict__ bkv)
{
    __shared__ alignas(16) char Bs[2][4096];

    int bx = blockIdx.x;
    int mode = (bx < 2) ? 0 : 1;
    const float* A = (mode == 0) ? Aq : Akv;
    const float* bias = (mode == 0) ? bq : bkv;
    int ldb  = (mode == 0) ? 256 : 512;
    int woff = (mode == 0) ? 0 : 65536;
    int col0 = ((mode == 0) ? bx : bx - 2) * 128;

    int tid = threadIdx.x;
    int lane = tid & 31, wid = tid >> 5;
    int warp_m = wid >> 1, warp_n = wid & 1;
    int row0 = blockIdx.y * 128;

    int k_b2 = tid >> 4;
    int n_b2 = (tid & 15) * 8;
    uint32_t offB = (uint32_t)k_b2*256u + (uint32_t)(((n_b2 >> 3) ^ (k_b2 & 7)) << 4);
    uint32_t stB[2];
    #pragma unroll
    for (int s = 0; s < 2; s++)
        stB[s] = (uint32_t)__cvta_generic_to_shared(&Bs[s][0]) + offB;
    int bk_lane = lane & 15;
    uint32_t bbase[2];
    #pragma unroll
    for (int s = 0; s < 2; s++)
        bbase[s] = (uint32_t)__cvta_generic_to_shared(&Bs[s][0]) + (uint32_t)bk_lane * 256u;
    int bkm = bk_lane & 7;

    const __half* Bh = g_wh + woff;

    const float* ap0 = A + (size_t)(row0 + warp_m*32 + (lane >> 2)) * DIM + (lane & 3) * 2;
    const float* ap1 = ap0 + 16 * DIM;

    float acc[2][8][4];
    #pragma unroll
    for (int mt = 0; mt < 2; mt++)
        #pragma unroll
        for (int nt = 0; nt < 8; nt++)
            #pragma unroll
            for (int i = 0; i < 4; i++) acc[mt][nt][i] = 0.f;

    float2 af[2][4];
#define LDA(kc)                                                         \
    {                                                                   \
        int kk = (kc) * 16;                                             \
        af[0][0] = *(const float2*)(ap0 + kk);                          \
        af[0][1] = *(const float2*)(ap0 + 8*DIM + kk);                  \
        af[0][2] = *(const float2*)(ap0 + kk + 8);                      \
        af[0][3] = *(const float2*)(ap0 + 8*DIM + kk + 8);              \
        af[1][0] = *(const float2*)(ap1 + kk);                          \
        af[1][1] = *(const float2*)(ap1 + 8*DIM + kk);                  \
        af[1][2] = *(const float2*)(ap1 + kk + 8);                      \
        af[1][3] = *(const float2*)(ap1 + 8*DIM + kk + 8);              \
    }

    cp16(stB[0], Bh + (size_t)k_b2 * ldb + col0 + n_b2);
    cp_commit();
    LDA(0);
    cp_wait0();
    __syncthreads();

    for (int kc = 0; kc < DIM/16; kc++) {
        int cur = kc & 1, nxt = cur ^ 1;
        bool has_next = (kc + 1 < DIM/16);

        if (has_next) {
            int k0 = (kc + 1) * 16;
            cp16(stB[nxt], Bh + (size_t)(k0 + k_b2) * ldb + col0 + n_b2);
            cp_commit();
        }

        uint32_t ah[2][4];
        #pragma unroll
        for (int mt = 0; mt < 2; mt++)
            #pragma unroll
            for (int j = 0; j < 4; j++)
                ah[mt][j] = pack2(af[mt][j].x, af[mt][j].y);

        if (has_next) LDA(kc + 1);

        #pragma unroll
        for (int nt = 0; nt < 8; nt++) {
            uint32_t boff = (uint32_t)(((warp_n*8 + nt) ^ bkm) << 4);
            uint32_t bh2[2];
            ldsm_x2t(bh2, bbase[cur] + boff);
            mma16816(acc[0][nt], ah[0], bh2);
            mma16816(acc[1][nt], ah[1], bh2);
        }

        if (has_next) cp_wait0();
        __syncthreads();
    }
#undef LDA

    const float scale = 0.17677669529663687f;
    #pragma unroll
    for (int mt = 0; mt < 2; mt++) {
        int rr = row0 + warp_m*32 + mt*16 + (lane >> 2);
        int bI = rr >> 6, nI = rr & 63;
        #pragma unroll
        for (int hg = 0; hg < 2; hg++) {
            int cg = col0 + warp_n*64 + hg*32;
            float sqA = 0.f, sqB = 0.f;
            uint32_t hwA[4], hwB[4];
            #pragma unroll
            for (int j = 0; j < 4; j++) {
                int nt = hg*4 + j;
                int c = cg + j*8 + 2*(lane & 3);
                float b0 = bias[c], b1 = bias[c+1];
                float v0 = acc[mt][nt][0]+b0, v1 = acc[mt][nt][1]+b1;
                float v2 = acc[mt][nt][2]+b0, v3 = acc[mt][nt][3]+b1;
                if (mode == 0) { v0*=scale; v1*=scale; v2*=scale; v3*=scale; }
                sqA += v0*v0 + v1*v1;
                sqB += v2*v2 + v3*v3;
                hwA[j] = pack2(v0, v1);
                hwB[j] = pack2(v2, v3);
            }
            sqA += __shfl_xor_sync(0xffffffffu, sqA, 1);
            sqA += __shfl_xor_sync(0xffffffffu, sqA, 2);
            sqB += __shfl_xor_sync(0xffffffffu, sqB, 1);
            sqB += __shfl_xor_sync(0xffffffffu, sqB, 2);

            uint32_t *dh;
            float* dn = nullptr;
            int hh;
            if (mode == 0)      { hh = cg >> 5;         dh = g_qh; dn = g_qn; }
            else if (cg < 256)  { hh = cg >> 5;         dh = g_kh; dn = g_kn; }
            else                { hh = (cg - 256) >> 5; dh = g_vh; }

            size_t wb = (((size_t)bI*HEADS + hh)*NTOK + nI)*16 + (lane & 3);
            #pragma unroll
            for (int j = 0; j < 4; j++) {
                dh[wb + j*4]        = hwA[j];
                dh[wb + 8*16 + j*4] = hwB[j];
            }
            if (dn && (lane & 3) == 0) {
                size_t nb = ((size_t)bI*HEADS + hh)*NTOK + nI;
                dn[nb]     = sqrtf(sqA);
                dn[nb + 8] = sqrtf(sqB);
            }
        }
    }
}

// ============================================================
// Kernel 2b: output projection GEMM — fp16 A via cp.async+ldsm
//   A smem tile: 128 rows x 32B (16 halves), unit swizzle u^( (r>>2)&1 )
// ============================================================
__global__ void __launch_bounds__(256, 2) p_gemm_kernel(
    const float* __restrict__ bias, float* __restrict__ D)
{
    __shared__ alignas(16) char As[2][4096];
    __shared__ alignas(16) char Bs[2][4096];

    int tid = threadIdx.x;
    int lane = tid & 31, wid = tid >> 5;
    int warp_m = wid >> 1, warp_n = wid & 1;
    int row0 = blockIdx.y * 128;
    int col0 = blockIdx.x * 128;
    const int ldb = 256;

    // B fill
    int k_b2 = tid >> 4;
    int n_b2 = (tid & 15) * 8;
    uint32_t offB = (uint32_t)k_b2*256u + (uint32_t)(((n_b2 >> 3) ^ (k_b2 & 7)) << 4);
    uint32_t stB[2], bbase[2];
    #pragma unroll
    for (int s = 0; s < 2; s++) {
        stB[s] = (uint32_t)__cvta_generic_to_shared(&Bs[s][0]) + offB;
        bbase[s] = (uint32_t)__cvta_generic_to_shared(&Bs[s][0]) + (uint32_t)(lane & 15) * 256u;
    }
    int bkm = lane & 7;

    // A fill: thread -> row=tid>>1, unit=tid&1
    int a_row = tid >> 1;
    int a_u   = tid & 1;
    uint32_t offA = (uint32_t)a_row*32u + (uint32_t)((a_u ^ ((a_row >> 2) & 1)) << 4);
    uint32_t stA[2];
    #pragma unroll
    for (int s = 0; s < 2; s++)
        stA[s] = (uint32_t)__cvta_generic_to_shared(&As[s][0]) + offA;
    const uint32_t* aop = g_aoh + (size_t)(row0 + a_row) * 128 + a_u * 4;

    // A ldsm lane addresses
    uint32_t aaddr[2][2];
    {
        int lrow_loc = ((lane >> 3) & 1) * 8 + (lane & 7);
        int lkh = lane >> 4;
        #pragma unroll
        for (int s = 0; s < 2; s++)
            #pragma unroll
            for (int mt = 0; mt < 2; mt++) {
                int m = warp_m * 32 + mt * 16 + lrow_loc;
                uint32_t off = (uint32_t)m * 32u + (uint32_t)((lkh ^ ((m >> 2) & 1)) << 4);
                aaddr[s][mt] = (uint32_t)__cvta_generic_to_shared(&As[s][0]) + off;
            }
    }

    const __half* Bh = g_wh + 196608;

    float acc[2][8][4];
    #pragma unroll
    for (int mt = 0; mt < 2; mt++)
        #pragma unroll
        for (int nt = 0; nt < 8; nt++)
            #pragma unroll
            for (int i = 0; i < 4; i++) acc[mt][nt][i] = 0.f;

    // prologue
    cp16(stA[0], aop);
    cp16(stB[0], Bh + (size_t)k_b2 * ldb + col0 + n_b2);
    cp_commit();
    cp_wait0();
    __syncthreads();

    for (int kc = 0; kc < DIM/16; kc++) {
        int cur = kc & 1, nxt = cur ^ 1;
        bool has_next = (kc + 1 < DIM/16);

        if (has_next) {
            int k0 = (kc + 1) * 16;
            cp16(stA[nxt], aop + (size_t)(kc + 1) * 8);
            cp16(stB[nxt], Bh + (size_t)(k0 + k_b2) * ldb + col0 + n_b2);
            cp_commit();
        }

        uint32_t ah[2][4];
        ldsm_x4(ah[0], aaddr[cur][0]);
        ldsm_x4(ah[1], aaddr[cur][1]);

        #pragma unroll
        for (int nt = 0; nt < 8; nt++) {
            uint32_t boff = (uint32_t)(((warp_n*8 + nt) ^ bkm) << 4);
            uint32_t bh2[2];
            ldsm_x2t(bh2, bbase[cur] + boff);
            mma16816(acc[0][nt], ah[0], bh2);
            mma16816(acc[1][nt], ah[1], bh2);
        }

        if (has_next) cp_wait0();
        __syncthreads();
    }

    #pragma unroll
    for (int mt = 0; mt < 2; mt++) {
        int r_base = row0 + warp_m*32 + mt*16 + (lane >> 2);
        #pragma unroll
        for (int nt = 0; nt < 8; nt++) {
            int c = col0 + warp_n*64 + nt*8 + 2*(lane & 3);
            float b0 = bias[c], b1 = bias[c+1];
            *(float2*)&D[(size_t)r_base*DIM + c] =
                make_float2(acc[mt][nt][0]+b0, acc[mt][nt][1]+b1);
            *(float2*)&D[(size_t)(r_base+8)*DIM + c] =
                make_float2(acc[mt][nt][2]+b0, acc[mt][nt][3]+b1);
        }
    }
}

// ============================================================
// Kernel 3: attention — fp16 q/k/v/P, packed fp16 output
// ============================================================
__global__ void __launch_bounds__(128) attn_mma_kernel(const float* __restrict__ mask)
{
    __shared__ alignas(16) char kvsm[8192];
    __shared__ float qn_s[NTOK], kn_s[NTOK];

    int b = blockIdx.x;
    int h = blockIdx.y;
    int w = b & 63;
    int tid = threadIdx.x;
    int lane = tid & 31, wid = tid >> 5;
    int mbase = wid * 16;

    uint32_t kvb = (uint32_t)__cvta_generic_to_shared(kvsm);

    const float* itp = g_invtau + h*4096;
    const float* bpp = g_bias   + h*4096;
    const float* mpp = mask + (size_t)w*4096;

    int r_ld = tid >> 1;
    int half = tid & 1;
    int swr = r_ld & 7;
    int ko0 = half * 2;

    size_t wb = (((size_t)b*HEADS + h)*NTOK + r_ld)*16 + half*8;
    size_t nb = ((size_t)b*HEADS + h)*NTOK;

    // ---- q fragments direct from gmem ----
    uint32_t qfh[2][4];
    {
        const uint32_t* qbh = g_qh + nb*16;
        int r0 = mbase + (lane >> 2);
        int wsel = lane & 3;
        #pragma unroll
        for (int kt = 0; kt < 2; kt++) {
            int w0 = kt*8 + wsel;
            qfh[kt][0] = qbh[r0*16 + w0];
            qfh[kt][1] = qbh[(r0+8)*16 + w0];
            qfh[kt][2] = qbh[r0*16 + w0 + 4];
            qfh[kt][3] = qbh[(r0+8)*16 + w0 + 4];
        }
    }

    // ---- fill k (units 0-3) and v (units 4-7) + norms ----
    {
        uint4 a0 = *(const uint4*)(g_kh + wb);
        uint4 a1 = *(const uint4*)(g_kh + wb + 4);
        uint4 b0 = *(const uint4*)(g_vh + wb);
        uint4 b1 = *(const uint4*)(g_vh + wb + 4);
        *(uint4*)(kvsm + r_ld*128 + (((ko0+0) ^ swr) << 4))     = a0;
        *(uint4*)(kvsm + r_ld*128 + (((ko0+1) ^ swr) << 4))     = a1;
        *(uint4*)(kvsm + r_ld*128 + (((4+ko0+0) ^ swr) << 4))   = b0;
        *(uint4*)(kvsm + r_ld*128 + (((4+ko0+1) ^ swr) << 4))   = b1;
        if (tid < 64) qn_s[tid] = g_qn[nb + tid];
        else          kn_s[tid - 64] = g_kn[nb + tid - 64];
    }
    __syncthreads();

    // ---- S = q k^T ----
    float sf[8][4];
    #pragma unroll
    for (int nt = 0; nt < 8; nt++)
        #pragma unroll
        for (int i = 0; i < 4; i++) sf[nt][i] = 0.f;

    #pragma unroll
    for (int kt = 0; kt < 2; kt++) {
        int krow_l = (lane & 7);
        int kko    = kt*2 + ((lane >> 3) & 1);
        uint32_t kbh[8][2];
        #pragma unroll
        for (int nt = 0; nt < 8; nt++) {
            int krow = nt*8 + krow_l;
            ldsm_x2(kbh[nt], kvb + krow*128 + ((kko ^ (krow & 7)) << 4));
        }
        #pragma unroll
        for (int nt = 0; nt < 8; nt++) mma16816(sf[nt], qfh[kt], kbh[nt]);
    }

    // ---- epilogue: cosine norm + tau + bias + mask ----
    int rA = mbase + (lane >> 2);
    int rB = rA + 8;
    float qnA = qn_s[rA], qnB = qn_s[rB];
    #pragma unroll
    for (int nt = 0; nt < 8; nt++) {
        int c0 = nt*8 + 2*(lane & 3);
        float2 kn2 = *(float2*)&kn_s[c0];
        int iA = rA*64 + c0, iB = rB*64 + c0;
        float2 tA = *(const float2*)(itp + iA);
        float2 tB = *(const float2*)(itp + iB);
        float2 bA = *(const float2*)(bpp + iA);
        float2 bB = *(const float2*)(bpp + iB);
        float2 mA = *(const float2*)(mpp + iA);
        float2 mB = *(const float2*)(mpp + iB);
        sf[nt][0] = __fdividef(sf[nt][0], fmaxf(qnA*kn2.x, 1e-6f)) * tA.x + bA.x + mA.x;
        sf[nt][1] = __fdividef(sf[nt][1], fmaxf(qnA*kn2.y, 1e-6f)) * tA.y + bA.y + mA.y;
        sf[nt][2] = __fdividef(sf[nt][2], fmaxf(qnB*kn2.x, 1e-6f)) * tB.x + bB.x + mB.x;
        sf[nt][3] = __fdividef(sf[nt][3], fmaxf(qnB*kn2.y, 1e-6f)) * tB.y + bB.y + mB.y;
    }

    // ---- fragment softmax ----
    {
        float mA = -1e30f, mB = -1e30f;
        #pragma unroll
        for (int nt = 0; nt < 8; nt++) {
            mA = fmaxf(mA, fmaxf(sf[nt][0], sf[nt][1]));
            mB = fmaxf(mB, fmaxf(sf[nt][2], sf[nt][3]));
        }
        mA = fmaxf(mA, __shfl_xor_sync(0xffffffffu, mA, 1));
        mA = fmaxf(mA, __shfl_xor_sync(0xffffffffu, mA, 2));
        mB = fmaxf(mB, __shfl_xor_sync(0xffffffffu, mB, 1));
        mB = fmaxf(mB, __shfl_xor_sync(0xffffffffu, mB, 2));
        float sA = 0.f, sB = 0.f;
        #pragma unroll
        for (int nt = 0; nt < 8; nt++) {
            sf[nt][0] = __expf(sf[nt][0] - mA); sA += sf[nt][0];
            sf[nt][1] = __expf(sf[nt][1] - mA); sA += sf[nt][1];
            sf[nt][2] = __expf(sf[nt][2] - mB); sB += sf[nt][2];
            sf[nt][3] = __expf(sf[nt][3] - mB); sB += sf[nt][3];
        }
        sA += __shfl_xor_sync(0xffffffffu, sA, 1);
        sA += __shfl_xor_sync(0xffffffffu, sA, 2);
        sB += __shfl_xor_sync(0xffffffffu, sB, 1);
        sB += __shfl_xor_sync(0xffffffffu, sB, 2);
        float iA2 = __fdividef(1.f, sA);
        float iB2 = __fdividef(1.f, sB);
        #pragma unroll
        for (int nt = 0; nt < 8; nt++) {
            sf[nt][0] *= iA2; sf[nt][1] *= iA2;
            sf[nt][2] *= iB2; sf[nt][3] *= iB2;
        }
    }

    // ---- O = P V (P single fp16) ----
    float of[4][4];
    #pragma unroll
    for (int nt = 0; nt < 4; nt++)
        #pragma unroll
        for (int i = 0; i < 4; i++) of[nt][i] = 0.f;

    #pragma unroll
    for (int kt2 = 0; kt2 < 4; kt2++) {
        int ntA = 2*kt2, ntB = 2*kt2 + 1;
        uint32_t pah[4];
        pah[0] = pack2(sf[ntA][0], sf[ntA][1]);
        pah[1] = pack2(sf[ntA][2], sf[ntA][3]);
        pah[2] = pack2(sf[ntB][0], sf[ntB][1]);
        pah[3] = pack2(sf[ntB][2], sf[ntB][3]);
        int vrow = kt2*16 + (lane & 15);
        int vsw = vrow & 7;
        uint32_t vbh[4][2];
        #pragma unroll
        for (int nt2 = 0; nt2 < 4; nt2++)
            ldsm_x2t(vbh[nt2], kvb + vrow*128 + (((4 + nt2) ^ vsw) << 4));
        #pragma unroll
        for (int nt2 = 0; nt2 < 4; nt2++) mma16816(of[nt2], pah, vbh[nt2]);
    }

    // ---- store O packed fp16 ----
    {
        uint32_t* obA = g_aoh + ((size_t)b*NTOK + rA)*128 + h*16 + (lane & 3);
        uint32_t* obB = g_aoh + ((size_t)b*NTOK + rB)*128 + h*16 + (lane & 3);
        #pragma unroll
        for (int nt2 = 0; nt2 < 4; nt2++) {
            obA[nt2*4] = pack2(of[nt2][0], of[nt2][1]);
            obB[nt2*4] = pack2(of[nt2][2], of[nt2][3]);
        }
    }
}

// ============================================================
// launch
// ============================================================
extern "C" void kernel_launch(void* const* d_in, const int* in_sizes, int n_in,
                              void* d_out, int out_size)
{
    const float* x      = (const float*)d_in[0];
    const float* KV     = (const float*)d_in[1];
    const float* mask   = (const float*)d_in[2];
    const float* Wq     = (const float*)d_in[3];
    const float* bq     = (const float*)d_in[4];
    const float* Wkv    = (const float*)d_in[5];
    const float* bkv    = (const float*)d_in[6];
    const float* Wp     = (const float*)d_in[7];
    const float* bp     = (const float*)d_in[8];
    const float* cpb_w1 = (const float*)d_in[9];
    const float* cpb_b1 = (const float*)d_in[10];
    const float* cpb_w2 = (const float*)d_in[11];
    const float* cpb_b2 = (const float*)d_in[12];
    const float* tau    = (const float*)d_in[13];
    const float* lri    = (const float*)d_in[14];
    float* out = (float*)d_out;

    const int MT = (BWIN * NTOK) / 128;   // 1024

    prep_kernel<<<1040, 256>>>(Wq, Wkv, Wp, cpb_w1, cpb_b1, cpb_w2, cpb_b2, tau, lri);
    qkv_gemm_kernel<<<dim3(6, MT), 256>>>(x, KV, bq, bkv);
    attn_mma_kernel<<<dim3(BWIN, HEADS), 128>>>(mask);
    p_gemm_kernel<<<dim3(2, MT), 256>>>(bp, out);
}

// round 16
// speedup vs baseline: 1.8722x; 1.2860x over previous
#include <cuda_runtime.h>
#include <cuda_fp16.h>
#include <cstdint>

#define BWIN 2048
#define NTOK 64
#define DIM  256
#define HEADS 8
#define HD   32
#define NW   64

// ---- scratch (device globals; no allocations allowed) ----
__device__ uint32_t g_xh [16777216];            // x  fp16 packed (128 words/row)
__device__ uint32_t g_kvh[16777216];            // KV fp16 packed
__device__ uint32_t g_qh[BWIN*HEADS*NTOK*16];
__device__ uint32_t g_kh[BWIN*HEADS*NTOK*16];
__device__ uint32_t g_vh[BWIN*HEADS*NTOK*16];
__device__ float    g_qn[BWIN*HEADS*NTOK];
__device__ float    g_kn[BWIN*HEADS*NTOK];
__device__ uint32_t g_aoh[BWIN*NTOK*128];       // attention out fp16 packed
__device__ float g_bt[HEADS*NTOK*NTOK*2];       // interleaved (invtau, bias)
__device__ __half g_wh[262144];                 // fp16 weights [Wq|Wkv|Wp]

// ============================================================
// helpers
// ============================================================
__device__ __forceinline__ void mma16816(float* c, const uint32_t* a, const uint32_t* b) {
    asm volatile("mma.sync.aligned.m16n8k16.row.col.f32.f16.f16.f32 "
        "{%0,%1,%2,%3}, {%4,%5,%6,%7}, {%8,%9}, {%0,%1,%2,%3};\n"
        : "+f"(c[0]), "+f"(c[1]), "+f"(c[2]), "+f"(c[3])
        : "r"(a[0]), "r"(a[1]), "r"(a[2]), "r"(a[3]), "r"(b[0]), "r"(b[1]));
}
__device__ __forceinline__ void ldsm_x4(uint32_t* r, uint32_t addr) {
    asm volatile("ldmatrix.sync.aligned.m8n8.x4.shared.b16 {%0,%1,%2,%3}, [%4];"
        : "=r"(r[0]), "=r"(r[1]), "=r"(r[2]), "=r"(r[3]) : "r"(addr));
}
__device__ __forceinline__ void ldsm_x2(uint32_t* r, uint32_t addr) {
    asm volatile("ldmatrix.sync.aligned.m8n8.x2.shared.b16 {%0,%1}, [%2];"
        : "=r"(r[0]), "=r"(r[1]) : "r"(addr));
}
__device__ __forceinline__ void ldsm_x2t(uint32_t* r, uint32_t addr) {
    asm volatile("ldmatrix.sync.aligned.m8n8.x2.trans.shared.b16 {%0,%1}, [%2];"
        : "=r"(r[0]), "=r"(r[1]) : "r"(addr));
}
__device__ __forceinline__ void cp16(uint32_t smem, const void* gmem) {
    asm volatile("cp.async.cg.shared.global [%0], [%1], 16;" :: "r"(smem), "l"(gmem));
}
__device__ __forceinline__ void cp_commit() { asm volatile("cp.async.commit_group;"); }
__device__ __forceinline__ void cp_wait0()  { asm volatile("cp.async.wait_group 0;"); }
__device__ __forceinline__ uint32_t pack2(float a, float b) {
    return ((uint32_t)__half_as_ushort(__float2half_rn(b)) << 16)
         | (uint32_t)__half_as_ushort(__float2half_rn(a));
}

// ============================================================
// Kernel 0: merged prep
//   blocks [0,1024): weight fp16 convert
//   blocks [1024,1040): CPB bias + invtau (interleaved table)
//   blocks [1040, 1040+32768): x / KV fp16 convert
// ============================================================
__global__ void prep_kernel(const float* __restrict__ Wq,
                            const float* __restrict__ Wkv,
                            const float* __restrict__ Wp,
                            const float* __restrict__ x_, const float* __restrict__ KV_,
                            const float* __restrict__ w1, const float* __restrict__ b1,
                            const float* __restrict__ w2, const float* __restrict__ b2,
                            const float* __restrict__ tau, const float* __restrict__ lri)
{
    if (blockIdx.x < 1024) {
        int i = blockIdx.x * 256 + threadIdx.x;
        float f;
        if (i < 65536) f = Wq[i];
        else if (i < 196608) f = Wkv[i - 65536];
        else f = Wp[i - 196608];
        g_wh[i] = __float2half_rn(f);
    } else if (blockIdx.x < 1040) {
        int idx = (blockIdx.x - 1024) * 256 + threadIdx.x;
        if (idx >= NTOK*NTOK) return;
        float r0 = lri[idx*2 + 0];
        float r1 = lri[idx*2 + 1];
        float acc[HEADS];
        #pragma unroll
        for (int h = 0; h < HEADS; h++) acc[h] = 0.f;
        for (int k = 0; k < 256; k++) {
            float hk = fmaxf(r0 * w1[k] + r1 * w1[256 + k] + b1[k], 0.f);
            #pragma unroll
            for (int h = 0; h < HEADS; h++) acc[h] += hk * w2[k*HEADS + h];
        }
        #pragma unroll
        for (int h = 0; h < HEADS; h++) {
            g_bt[(h*NTOK*NTOK + idx)*2 + 0] = 1.0f / fmaxf(tau[h*NTOK*NTOK + idx], 0.01f);
            g_bt[(h*NTOK*NTOK + idx)*2 + 1] = acc[h] + b2[h];
        }
    } else {
        int j = blockIdx.x - 1040;          // 0..32767
        int arr = j >> 14;                  // 0: x, 1: KV
        size_t idx = (size_t)(j & 16383) * 256 + threadIdx.x;  // group of 4 words
        const float* src = arr ? KV_ : x_;
        uint32_t* dst = arr ? g_kvh : g_xh;
        float4 f0 = *(const float4*)(src + idx*8);
        float4 f1 = *(const float4*)(src + idx*8 + 4);
        uint4 o;
        o.x = pack2(f0.x, f0.y);
        o.y = pack2(f0.z, f0.w);
        o.z = pack2(f1.x, f1.y);
        o.w = pack2(f1.z, f1.w);
        *(uint4*)(dst + idx*4) = o;
    }
}

// ============================================================
// Kernel 2a: fused Q+KV projection GEMM — fp16 A via cp.async+ldsm
// ============================================================
__global__ void __launch_bounds__(256, 2) qkv_gemm_kernel(
    const float* __restrict__ bq, const float* __restrict__ bkv)
{
    __shared__ alignas(16) char As[2][4096];
    __shared__ alignas(16) char Bs[2][4096];

    int bx = blockIdx.x;
    int mode = (bx < 2) ? 0 : 1;
    const uint32_t* Asrc = mode ? g_kvh : g_xh;
    const float* bias = (mode == 0) ? bq : bkv;
    int ldb  = (mode == 0) ? 256 : 512;
    int woff = (mode == 0) ? 0 : 65536;
    int col0 = ((mode == 0) ? bx : bx - 2) * 128;

    int tid = threadIdx.x;
    int lane = tid & 31, wid = tid >> 5;
    int warp_m = wid >> 1, warp_n = wid & 1;
    int row0 = blockIdx.y * 128;

    // B fill
    int k_b2 = tid >> 4;
    int n_b2 = (tid & 15) * 8;
    uint32_t offB = (uint32_t)k_b2*256u + (uint32_t)(((n_b2 >> 3) ^ (k_b2 & 7)) << 4);
    uint32_t stB[2], bbase[2];
    #pragma unroll
    for (int s = 0; s < 2; s++) {
        stB[s] = (uint32_t)__cvta_generic_to_shared(&Bs[s][0]) + offB;
        bbase[s] = (uint32_t)__cvta_generic_to_shared(&Bs[s][0]) + (uint32_t)(lane & 15) * 256u;
    }
    int bkm = lane & 7;

    // A fill
    int a_row = tid >> 1;
    int a_u   = tid & 1;
    uint32_t offA = (uint32_t)a_row*32u + (uint32_t)((a_u ^ ((a_row >> 2) & 1)) << 4);
    uint32_t stA[2];
    #pragma unroll
    for (int s = 0; s < 2; s++)
        stA[s] = (uint32_t)__cvta_generic_to_shared(&As[s][0]) + offA;
    const uint32_t* aop = Asrc + (size_t)(row0 + a_row) * 128 + a_u * 4;

    // A ldsm lane addresses
    uint32_t aaddr[2][2];
    {
        int lrow_loc = ((lane >> 3) & 1) * 8 + (lane & 7);
        int lkh = lane >> 4;
        #pragma unroll
        for (int s = 0; s < 2; s++)
            #pragma unroll
            for (int mt = 0; mt < 2; mt++) {
                int m = warp_m * 32 + mt * 16 + lrow_loc;
                uint32_t off = (uint32_t)m * 32u + (uint32_t)((lkh ^ ((m >> 2) & 1)) << 4);
                aaddr[s][mt] = (uint32_t)__cvta_generic_to_shared(&As[s][0]) + off;
            }
    }

    const __half* Bh = g_wh + woff;

    float acc[2][8][4];
    #pragma unroll
    for (int mt = 0; mt < 2; mt++)
        #pragma unroll
        for (int nt = 0; nt < 8; nt++)
            #pragma unroll
            for (int i = 0; i < 4; i++) acc[mt][nt][i] = 0.f;

    // prologue
    cp16(stA[0], aop);
    cp16(stB[0], Bh + (size_t)k_b2 * ldb + col0 + n_b2);
    cp_commit();
    cp_wait0();
    __syncthreads();

    for (int kc = 0; kc < DIM/16; kc++) {
        int cur = kc & 1, nxt = cur ^ 1;
        bool has_next = (kc + 1 < DIM/16);

        if (has_next) {
            int k0 = (kc + 1) * 16;
            cp16(stA[nxt], aop + (size_t)(kc + 1) * 8);
            cp16(stB[nxt], Bh + (size_t)(k0 + k_b2) * ldb + col0 + n_b2);
            cp_commit();
        }

        uint32_t ah[2][4];
        ldsm_x4(ah[0], aaddr[cur][0]);
        ldsm_x4(ah[1], aaddr[cur][1]);

        #pragma unroll
        for (int nt = 0; nt < 8; nt++) {
            uint32_t boff = (uint32_t)(((warp_n*8 + nt) ^ bkm) << 4);
            uint32_t bh2[2];
            ldsm_x2t(bh2, bbase[cur] + boff);
            mma16816(acc[0][nt], ah[0], bh2);
            mma16816(acc[1][nt], ah[1], bh2);
        }

        if (has_next) cp_wait0();
        __syncthreads();
    }

    const float scale = 0.17677669529663687f;
    #pragma unroll
    for (int mt = 0; mt < 2; mt++) {
        int rr = row0 + warp_m*32 + mt*16 + (lane >> 2);
        int bI = rr >> 6, nI = rr & 63;
        #pragma unroll
        for (int hg = 0; hg < 2; hg++) {
            int cg = col0 + warp_n*64 + hg*32;
            float sqA = 0.f, sqB = 0.f;
            uint32_t hwA[4], hwB[4];
            #pragma unroll
            for (int j = 0; j < 4; j++) {
                int nt = hg*4 + j;
                int c = cg + j*8 + 2*(lane & 3);
                float b0 = bias[c], b1 = bias[c+1];
                float v0 = acc[mt][nt][0]+b0, v1 = acc[mt][nt][1]+b1;
                float v2 = acc[mt][nt][2]+b0, v3 = acc[mt][nt][3]+b1;
                if (mode == 0) { v0*=scale; v1*=scale; v2*=scale; v3*=scale; }
                sqA += v0*v0 + v1*v1;
                sqB += v2*v2 + v3*v3;
                hwA[j] = pack2(v0, v1);
                hwB[j] = pack2(v2, v3);
            }
            sqA += __shfl_xor_sync(0xffffffffu, sqA, 1);
            sqA += __shfl_xor_sync(0xffffffffu, sqA, 2);
            sqB += __shfl_xor_sync(0xffffffffu, sqB, 1);
            sqB += __shfl_xor_sync(0xffffffffu, sqB, 2);

            uint32_t *dh;
            float* dn = nullptr;
            int hh;
            if (mode == 0)      { hh = cg >> 5;         dh = g_qh; dn = g_qn; }
            else if (cg < 256)  { hh = cg >> 5;         dh = g_kh; dn = g_kn; }
            else                { hh = (cg - 256) >> 5; dh = g_vh; }

            size_t wb = (((size_t)bI*HEADS + hh)*NTOK + nI)*16 + (lane & 3);
            #pragma unroll
            for (int j = 0; j < 4; j++) {
                dh[wb + j*4]        = hwA[j];
                dh[wb + 8*16 + j*4] = hwB[j];
            }
            if (dn && (lane & 3) == 0) {
                size_t nb = ((size_t)bI*HEADS + hh)*NTOK + nI;
                dn[nb]     = sqrtf(sqA);
                dn[nb + 8] = sqrtf(sqB);
            }
        }
    }
}

// ============================================================
// Kernel 2b: output projection GEMM — fp16 A via cp.async+ldsm
// ============================================================
__global__ void __launch_bounds__(256, 2) p_gemm_kernel(
    const float* __restrict__ bias, float* __restrict__ D)
{
    __shared__ alignas(16) char As[2][4096];
    __shared__ alignas(16) char Bs[2][4096];

    int tid = threadIdx.x;
    int lane = tid & 31, wid = tid >> 5;
    int warp_m = wid >> 1, warp_n = wid & 1;
    int row0 = blockIdx.y * 128;
    int col0 = blockIdx.x * 128;
    const int ldb = 256;

    int k_b2 = tid >> 4;
    int n_b2 = (tid & 15) * 8;
    uint32_t offB = (uint32_t)k_b2*256u + (uint32_t)(((n_b2 >> 3) ^ (k_b2 & 7)) << 4);
    uint32_t stB[2], bbase[2];
    #pragma unroll
    for (int s = 0; s < 2; s++) {
        stB[s] = (uint32_t)__cvta_generic_to_shared(&Bs[s][0]) + offB;
        bbase[s] = (uint32_t)__cvta_generic_to_shared(&Bs[s][0]) + (uint32_t)(lane & 15) * 256u;
    }
    int bkm = lane & 7;

    int a_row = tid >> 1;
    int a_u   = tid & 1;
    uint32_t offA = (uint32_t)a_row*32u + (uint32_t)((a_u ^ ((a_row >> 2) & 1)) << 4);
    uint32_t stA[2];
    #pragma unroll
    for (int s = 0; s < 2; s++)
        stA[s] = (uint32_t)__cvta_generic_to_shared(&As[s][0]) + offA;
    const uint32_t* aop = g_aoh + (size_t)(row0 + a_row) * 128 + a_u * 4;

    uint32_t aaddr[2][2];
    {
        int lrow_loc = ((lane >> 3) & 1) * 8 + (lane & 7);
        int lkh = lane >> 4;
        #pragma unroll
        for (int s = 0; s < 2; s++)
            #pragma unroll
            for (int mt = 0; mt < 2; mt++) {
                int m = warp_m * 32 + mt * 16 + lrow_loc;
                uint32_t off = (uint32_t)m * 32u + (uint32_t)((lkh ^ ((m >> 2) & 1)) << 4);
                aaddr[s][mt] = (uint32_t)__cvta_generic_to_shared(&As[s][0]) + off;
            }
    }

    const __half* Bh = g_wh + 196608;

    float acc[2][8][4];
    #pragma unroll
    for (int mt = 0; mt < 2; mt++)
        #pragma unroll
        for (int nt = 0; nt < 8; nt++)
            #pragma unroll
            for (int i = 0; i < 4; i++) acc[mt][nt][i] = 0.f;

    cp16(stA[0], aop);
    cp16(stB[0], Bh + (size_t)k_b2 * ldb + col0 + n_b2);
    cp_commit();
    cp_wait0();
    __syncthreads();

    for (int kc = 0; kc < DIM/16; kc++) {
        int cur = kc & 1, nxt = cur ^ 1;
        bool has_next = (kc + 1 < DIM/16);

        if (has_next) {
            int k0 = (kc + 1) * 16;
            cp16(stA[nxt], aop + (size_t)(kc + 1) * 8);
            cp16(stB[nxt], Bh + (size_t)(k0 + k_b2) * ldb + col0 + n_b2);
            cp_commit();
        }

        uint32_t ah[2][4];
        ldsm_x4(ah[0], aaddr[cur][0]);
        ldsm_x4(ah[1], aaddr[cur][1]);

        #pragma unroll
        for (int nt = 0; nt < 8; nt++) {
            uint32_t boff = (uint32_t)(((warp_n*8 + nt) ^ bkm) << 4);
            uint32_t bh2[2];
            ldsm_x2t(bh2, bbase[cur] + boff);
            mma16816(acc[0][nt], ah[0], bh2);
            mma16816(acc[1][nt], ah[1], bh2);
        }

        if (has_next) cp_wait0();
        __syncthreads();
    }

    #pragma unroll
    for (int mt = 0; mt < 2; mt++) {
        int r_base = row0 + warp_m*32 + mt*16 + (lane >> 2);
        #pragma unroll
        for (int nt = 0; nt < 8; nt++) {
            int c = col0 + warp_n*64 + nt*8 + 2*(lane & 3);
            float b0 = bias[c], b1 = bias[c+1];
            *(float2*)&D[(size_t)r_base*DIM + c] =
                make_float2(acc[mt][nt][0]+b0, acc[mt][nt][1]+b1);
            *(float2*)&D[(size_t)(r_base+8)*DIM + c] =
                make_float2(acc[mt][nt][2]+b0, acc[mt][nt][3]+b1);
        }
    }
}

// ============================================================
// Kernel 3: attention — fp16 q/k/v/P, merged (invtau,bias) table
// ============================================================
__global__ void __launch_bounds__(128) attn_mma_kernel(const float* __restrict__ mask)
{
    __shared__ alignas(16) char kvsm[8192];
    __shared__ float qn_s[NTOK], kn_s[NTOK];

    int b = blockIdx.x;
    int h = blockIdx.y;
    int w = b & 63;
    int tid = threadIdx.x;
    int lane = tid & 31, wid = tid >> 5;
    int mbase = wid * 16;

    uint32_t kvb = (uint32_t)__cvta_generic_to_shared(kvsm);

    const float* btp = g_bt + (size_t)h*8192;
    const float* mpp = mask + (size_t)w*4096;

    int r_ld = tid >> 1;
    int half = tid & 1;
    int swr = r_ld & 7;
    int ko0 = half * 2;

    size_t wb = (((size_t)b*HEADS + h)*NTOK + r_ld)*16 + half*8;
    size_t nb = ((size_t)b*HEADS + h)*NTOK;

    // ---- q fragments direct from gmem ----
    uint32_t qfh[2][4];
    {
        const uint32_t* qbh = g_qh + nb*16;
        int r0 = mbase + (lane >> 2);
        int wsel = lane & 3;
        #pragma unroll
        for (int kt = 0; kt < 2; kt++) {
            int w0 = kt*8 + wsel;
            qfh[kt][0] = qbh[r0*16 + w0];
            qfh[kt][1] = qbh[(r0+8)*16 + w0];
            qfh[kt][2] = qbh[r0*16 + w0 + 4];
            qfh[kt][3] = qbh[(r0+8)*16 + w0 + 4];
        }
    }

    // ---- fill k (units 0-3) and v (units 4-7) + norms ----
    {
        uint4 a0 = *(const uint4*)(g_kh + wb);
        uint4 a1 = *(const uint4*)(g_kh + wb + 4);
        uint4 b0 = *(const uint4*)(g_vh + wb);
        uint4 b1 = *(const uint4*)(g_vh + wb + 4);
        *(uint4*)(kvsm + r_ld*128 + (((ko0+0) ^ swr) << 4))     = a0;
        *(uint4*)(kvsm + r_ld*128 + (((ko0+1) ^ swr) << 4))     = a1;
        *(uint4*)(kvsm + r_ld*128 + (((4+ko0+0) ^ swr) << 4))   = b0;
        *(uint4*)(kvsm + r_ld*128 + (((4+ko0+1) ^ swr) << 4))   = b1;
        if (tid < 64) qn_s[tid] = g_qn[nb + tid];
        else          kn_s[tid - 64] = g_kn[nb + tid - 64];
    }
    __syncthreads();

    // ---- S = q k^T ----
    float sf[8][4];
    #pragma unroll
    for (int nt = 0; nt < 8; nt++)
        #pragma unroll
        for (int i = 0; i < 4; i++) sf[nt][i] = 0.f;

    #pragma unroll
    for (int kt = 0; kt < 2; kt++) {
        int krow_l = (lane & 7);
        int kko    = kt*2 + ((lane >> 3) & 1);
        uint32_t kbh[8][2];
        #pragma unroll
        for (int nt = 0; nt < 8; nt++) {
            int krow = nt*8 + krow_l;
            ldsm_x2(kbh[nt], kvb + krow*128 + ((kko ^ (krow & 7)) << 4));
        }
        #pragma unroll
        for (int nt = 0; nt < 8; nt++) mma16816(sf[nt], qfh[kt], kbh[nt]);
    }

    // ---- epilogue: cosine norm + tau + bias + mask ----
    int rA = mbase + (lane >> 2);
    int rB = rA + 8;
    float qnA = qn_s[rA], qnB = qn_s[rB];
    #pragma unroll
    for (int nt = 0; nt < 8; nt++) {
        int c0 = nt*8 + 2*(lane & 3);
        float2 kn2 = *(float2*)&kn_s[c0];
        int iA = rA*64 + c0, iB = rB*64 + c0;
        float4 tbA = *(const float4*)(btp + iA*2);   // (it0,b0,it1,b1)
        float4 tbB = *(const float4*)(btp + iB*2);
        float2 mA = *(const float2*)(mpp + iA);
        float2 mB = *(const float2*)(mpp + iB);
        sf[nt][0] = __fdividef(sf[nt][0], fmaxf(qnA*kn2.x, 1e-6f)) * tbA.x + tbA.y + mA.x;
        sf[nt][1] = __fdividef(sf[nt][1], fmaxf(qnA*kn2.y, 1e-6f)) * tbA.z + tbA.w + mA.y;
        sf[nt][2] = __fdividef(sf[nt][2], fmaxf(qnB*kn2.x, 1e-6f)) * tbB.x + tbB.y + mB.x;
        sf[nt][3] = __fdividef(sf[nt][3], fmaxf(qnB*kn2.y, 1e-6f)) * tbB.z + tbB.w + mB.y;
    }

    // ---- fragment softmax ----
    {
        float mA = -1e30f, mB = -1e30f;
        #pragma unroll
        for (int nt = 0; nt < 8; nt++) {
            mA = fmaxf(mA, fmaxf(sf[nt][0], sf[nt][1]));
            mB = fmaxf(mB, fmaxf(sf[nt][2], sf[nt][3]));
        }
        mA = fmaxf(mA, __shfl_xor_sync(0xffffffffu, mA, 1));
        mA = fmaxf(mA, __shfl_xor_sync(0xffffffffu, mA, 2));
        mB = fmaxf(mB, __shfl_xor_sync(0xffffffffu, mB, 1));
        mB = fmaxf(mB, __shfl_xor_sync(0xffffffffu, mB, 2));
        float sA = 0.f, sB = 0.f;
        #pragma unroll
        for (int nt = 0; nt < 8; nt++) {
            sf[nt][0] = __expf(sf[nt][0] - mA); sA += sf[nt][0];
            sf[nt][1] = __expf(sf[nt][1] - mA); sA += sf[nt][1];
            sf[nt][2] = __expf(sf[nt][2] - mB); sB += sf[nt][2];
            sf[nt][3] = __expf(sf[nt][3] - mB); sB += sf[nt][3];
        }
        sA += __shfl_xor_sync(0xffffffffu, sA, 1);
        sA += __shfl_xor_sync(0xffffffffu, sA, 2);
        sB += __shfl_xor_sync(0xffffffffu, sB, 1);
        sB += __shfl_xor_sync(0xffffffffu, sB, 2);
        float iA2 = __fdividef(1.f, sA);
        float iB2 = __fdividef(1.f, sB);
        #pragma unroll
        for (int nt = 0; nt < 8; nt++) {
            sf[nt][0] *= iA2; sf[nt][1] *= iA2;
            sf[nt][2] *= iB2; sf[nt][3] *= iB2;
        }
    }

    // ---- O = P V ----
    float of[4][4];
    #pragma unroll
    for (int nt = 0; nt < 4; nt++)
        #pragma unroll
        for (int i = 0; i < 4; i++) of[nt][i] = 0.f;

    #pragma unroll
    for (int kt2 = 0; kt2 < 4; kt2++) {
        int ntA = 2*kt2, ntB = 2*kt2 + 1;
        uint32_t pah[4];
        pah[0] = pack2(sf[ntA][0], sf[ntA][1]);
        pah[1] = pack2(sf[ntA][2], sf[ntA][3]);
        pah[2] = pack2(sf[ntB][0], sf[ntB][1]);
        pah[3] = pack2(sf[ntB][2], sf[ntB][3]);
        int vrow = kt2*16 + (lane & 15);
        int vsw = vrow & 7;
        uint32_t vbh[4][2];
        #pragma unroll
        for (int nt2 = 0; nt2 < 4; nt2++)
            ldsm_x2t(vbh[nt2], kvb + vrow*128 + (((4 + nt2) ^ vsw) << 4));
        #pragma unroll
        for (int nt2 = 0; nt2 < 4; nt2++) mma16816(of[nt2], pah, vbh[nt2]);
    }

    // ---- store O packed fp16 ----
    {
        uint32_t* obA = g_aoh + ((size_t)b*NTOK + rA)*128 + h*16 + (lane & 3);
        uint32_t* obB = g_aoh + ((size_t)b*NTOK + rB)*128 + h*16 + (lane & 3);
        #pragma unroll
        for (int nt2 = 0; nt2 < 4; nt2++) {
            obA[nt2*4] = pack2(of[nt2][0], of[nt2][1]);
            obB[nt2*4] = pack2(of[nt2][2], of[nt2][3]);
        }
    }
}

// ============================================================
// launch
// ============================================================
extern "C" void kernel_launch(void* const* d_in, const int* in_sizes, int n_in,
                              void* d_out, int out_size)
{
    const float* x      = (const float*)d_in[0];
    const float* KV     = (const float*)d_in[1];
    const float* mask   = (const float*)d_in[2];
    const float* Wq     = (const float*)d_in[3];
    const float* bq     = (const float*)d_in[4];
    const float* Wkv    = (const float*)d_in[5];
    const float* bkv    = (const float*)d_in[6];
    const float* Wp     = (const float*)d_in[7];
    const float* bp     = (const float*)d_in[8];
    const float* cpb_w1 = (const float*)d_in[9];
    const float* cpb_b1 = (const float*)d_in[10];
    const float* cpb_w2 = (const float*)d_in[11];
    const float* cpb_b2 = (const float*)d_in[12];
    const float* tau    = (const float*)d_in[13];
    const float* lri    = (const float*)d_in[14];
    float* out = (float*)d_out;

    const int MT = (BWIN * NTOK) / 128;   // 1024

    prep_kernel<<<1040 + 32768, 256>>>(Wq, Wkv, Wp, x, KV,
                                       cpb_w1, cpb_b1, cpb_w2, cpb_b2, tau, lri);
    qkv_gemm_kernel<<<dim3(6, MT), 256>>>(bq, bkv);
    attn_mma_kernel<<<dim3(BWIN, HEADS), 128>>>(mask);
    p_gemm_kernel<<<dim3(2, MT), 256>>>(bp, out);
}

// round 17
// speedup vs baseline: 2.0364x; 1.0877x over previous
#include <cuda_runtime.h>
#include <cuda_fp16.h>
#include <cstdint>

#define BWIN 2048
#define NTOK 64
#define DIM  256
#define HEADS 8
#define HD   32
#define NW   64

// ---- scratch (device globals; no allocations allowed) ----
__device__ uint32_t g_xh [16777216];            // x  fp16 packed (128 words/row)
__device__ uint32_t g_kvh[16777216];            // KV fp16 packed
__device__ uint32_t g_qh[BWIN*HEADS*NTOK*16];
__device__ uint32_t g_kh[BWIN*HEADS*NTOK*16];
__device__ uint32_t g_vh[BWIN*HEADS*NTOK*16];
__device__ float    g_qn[BWIN*HEADS*NTOK];
__device__ float    g_kn[BWIN*HEADS*NTOK];
__device__ uint32_t g_aoh[BWIN*NTOK*128];       // attention out fp16 packed
__device__ float g_bt[HEADS*NTOK*NTOK*2];       // interleaved (invtau, bias)
__device__ __half g_wh[262144];                 // fp16 weights [Wq|Wkv|Wp]

// ============================================================
// helpers
// ============================================================
__device__ __forceinline__ void mma16816(float* c, const uint32_t* a, const uint32_t* b) {
    asm volatile("mma.sync.aligned.m16n8k16.row.col.f32.f16.f16.f32 "
        "{%0,%1,%2,%3}, {%4,%5,%6,%7}, {%8,%9}, {%0,%1,%2,%3};\n"
        : "+f"(c[0]), "+f"(c[1]), "+f"(c[2]), "+f"(c[3])
        : "r"(a[0]), "r"(a[1]), "r"(a[2]), "r"(a[3]), "r"(b[0]), "r"(b[1]));
}
__device__ __forceinline__ void ldsm_x4(uint32_t* r, uint32_t addr) {
    asm volatile("ldmatrix.sync.aligned.m8n8.x4.shared.b16 {%0,%1,%2,%3}, [%4];"
        : "=r"(r[0]), "=r"(r[1]), "=r"(r[2]), "=r"(r[3]) : "r"(addr));
}
__device__ __forceinline__ void ldsm_x2(uint32_t* r, uint32_t addr) {
    asm volatile("ldmatrix.sync.aligned.m8n8.x2.shared.b16 {%0,%1}, [%2];"
        : "=r"(r[0]), "=r"(r[1]) : "r"(addr));
}
__device__ __forceinline__ void ldsm_x2t(uint32_t* r, uint32_t addr) {
    asm volatile("ldmatrix.sync.aligned.m8n8.x2.trans.shared.b16 {%0,%1}, [%2];"
        : "=r"(r[0]), "=r"(r[1]) : "r"(addr));
}
__device__ __forceinline__ void cp16(uint32_t smem, const void* gmem) {
    asm volatile("cp.async.cg.shared.global [%0], [%1], 16;" :: "r"(smem), "l"(gmem));
}
__device__ __forceinline__ void cp_commit() { asm volatile("cp.async.commit_group;"); }
__device__ __forceinline__ void cp_wait1()  { asm volatile("cp.async.wait_group 1;"); }
__device__ __forceinline__ uint32_t pack2(float a, float b) {
    return ((uint32_t)__half_as_ushort(__float2half_rn(b)) << 16)
         | (uint32_t)__half_as_ushort(__float2half_rn(a));
}

// ============================================================
// Kernel 0: merged prep (weights + bias table + x/KV fp16)
// ============================================================
__global__ void prep_kernel(const float* __restrict__ Wq,
                            const float* __restrict__ Wkv,
                            const float* __restrict__ Wp,
                            const float* __restrict__ x_, const float* __restrict__ KV_,
                            const float* __restrict__ w1, const float* __restrict__ b1,
                            const float* __restrict__ w2, const float* __restrict__ b2,
                            const float* __restrict__ tau, const float* __restrict__ lri)
{
    if (blockIdx.x < 1024) {
        int i = blockIdx.x * 256 + threadIdx.x;
        float f;
        if (i < 65536) f = Wq[i];
        else if (i < 196608) f = Wkv[i - 65536];
        else f = Wp[i - 196608];
        g_wh[i] = __float2half_rn(f);
    } else if (blockIdx.x < 1040) {
        int idx = (blockIdx.x - 1024) * 256 + threadIdx.x;
        if (idx >= NTOK*NTOK) return;
        float r0 = lri[idx*2 + 0];
        float r1 = lri[idx*2 + 1];
        float acc[HEADS];
        #pragma unroll
        for (int h = 0; h < HEADS; h++) acc[h] = 0.f;
        for (int k = 0; k < 256; k++) {
            float hk = fmaxf(r0 * w1[k] + r1 * w1[256 + k] + b1[k], 0.f);
            #pragma unroll
            for (int h = 0; h < HEADS; h++) acc[h] += hk * w2[k*HEADS + h];
        }
        #pragma unroll
        for (int h = 0; h < HEADS; h++) {
            g_bt[(h*NTOK*NTOK + idx)*2 + 0] = 1.0f / fmaxf(tau[h*NTOK*NTOK + idx], 0.01f);
            g_bt[(h*NTOK*NTOK + idx)*2 + 1] = acc[h] + b2[h];
        }
    } else {
        int j = blockIdx.x - 1040;
        int arr = j >> 14;
        size_t idx = (size_t)(j & 16383) * 256 + threadIdx.x;
        const float* src = arr ? KV_ : x_;
        uint32_t* dst = arr ? g_kvh : g_xh;
        float4 f0 = *(const float4*)(src + idx*8);
        float4 f1 = *(const float4*)(src + idx*8 + 4);
        uint4 o;
        o.x = pack2(f0.x, f0.y);
        o.y = pack2(f0.z, f0.w);
        o.z = pack2(f1.x, f1.y);
        o.w = pack2(f1.z, f1.w);
        *(uint4*)(dst + idx*4) = o;
    }
}

// ============================================================
// Kernel 2a: fused Q+KV projection GEMM — 3-stage cp.async
// ============================================================
__global__ void __launch_bounds__(256, 2) qkv_gemm_kernel(
    const float* __restrict__ bq, const float* __restrict__ bkv)
{
    __shared__ alignas(16) char As[3][4096];
    __shared__ alignas(16) char Bs[3][4096];

    int bx = blockIdx.x;
    int mode = (bx < 2) ? 0 : 1;
    const uint32_t* Asrc = mode ? g_kvh : g_xh;
    const float* bias = (mode == 0) ? bq : bkv;
    int ldb  = (mode == 0) ? 256 : 512;
    int woff = (mode == 0) ? 0 : 65536;
    int col0 = ((mode == 0) ? bx : bx - 2) * 128;

    int tid = threadIdx.x;
    int lane = tid & 31, wid = tid >> 5;
    int warp_m = wid >> 1, warp_n = wid & 1;
    int row0 = blockIdx.y * 128;

    // B fill
    int k_b2 = tid >> 4;
    int n_b2 = (tid & 15) * 8;
    uint32_t offB = (uint32_t)k_b2*256u + (uint32_t)(((n_b2 >> 3) ^ (k_b2 & 7)) << 4);
    uint32_t stB[3], bbase[3];
    #pragma unroll
    for (int s = 0; s < 3; s++) {
        stB[s] = (uint32_t)__cvta_generic_to_shared(&Bs[s][0]) + offB;
        bbase[s] = (uint32_t)__cvta_generic_to_shared(&Bs[s][0]) + (uint32_t)(lane & 15) * 256u;
    }
    int bkm = lane & 7;

    // A fill
    int a_row = tid >> 1;
    int a_u   = tid & 1;
    uint32_t offA = (uint32_t)a_row*32u + (uint32_t)((a_u ^ ((a_row >> 2) & 1)) << 4);
    uint32_t stA[3];
    #pragma unroll
    for (int s = 0; s < 3; s++)
        stA[s] = (uint32_t)__cvta_generic_to_shared(&As[s][0]) + offA;
    const uint32_t* aop = Asrc + (size_t)(row0 + a_row) * 128 + a_u * 4;

    // A ldsm lane addresses
    uint32_t aaddr[3][2];
    {
        int lrow_loc = ((lane >> 3) & 1) * 8 + (lane & 7);
        int lkh = lane >> 4;
        #pragma unroll
        for (int s = 0; s < 3; s++)
            #pragma unroll
            for (int mt = 0; mt < 2; mt++) {
                int m = warp_m * 32 + mt * 16 + lrow_loc;
                uint32_t off = (uint32_t)m * 32u + (uint32_t)((lkh ^ ((m >> 2) & 1)) << 4);
                aaddr[s][mt] = (uint32_t)__cvta_generic_to_shared(&As[s][0]) + off;
            }
    }

    const __half* Bh = g_wh + woff;

    float acc[2][8][4];
    #pragma unroll
    for (int mt = 0; mt < 2; mt++)
        #pragma unroll
        for (int nt = 0; nt < 8; nt++)
            #pragma unroll
            for (int i = 0; i < 4; i++) acc[mt][nt][i] = 0.f;

#define CPQ(kc, s)                                                       \
    {                                                                    \
        cp16(stA[s], aop + (size_t)(kc) * 8);                            \
        cp16(stB[s], Bh + (size_t)((kc)*16 + k_b2) * ldb + col0 + n_b2); \
        cp_commit();                                                     \
    }

    // prologue: 2 chunks in flight
    CPQ(0, 0)
    CPQ(1, 1)

    for (int kc = 0; kc < DIM/16; kc++) {
        int cur = kc % 3;
        cp_wait1();          // chunk kc complete (≤1 pending = kc+1)
        __syncthreads();

        uint32_t ah[2][4];
        ldsm_x4(ah[0], aaddr[cur][0]);
        ldsm_x4(ah[1], aaddr[cur][1]);

        #pragma unroll
        for (int nt = 0; nt < 8; nt++) {
            uint32_t boff = (uint32_t)(((warp_n*8 + nt) ^ bkm) << 4);
            uint32_t bh2[2];
            ldsm_x2t(bh2, bbase[cur] + boff);
            mma16816(acc[0][nt], ah[0], bh2);
            mma16816(acc[1][nt], ah[1], bh2);
        }

        if (kc + 2 < DIM/16) {
            int s = (kc + 2) % 3;
            CPQ(kc + 2, s)
        } else {
            cp_commit();    // keep group count consistent for wait_group 1
        }
    }
#undef CPQ

    const float scale = 0.17677669529663687f;
    #pragma unroll
    for (int mt = 0; mt < 2; mt++) {
        int rr = row0 + warp_m*32 + mt*16 + (lane >> 2);
        int bI = rr >> 6, nI = rr & 63;
        #pragma unroll
        for (int hg = 0; hg < 2; hg++) {
            int cg = col0 + warp_n*64 + hg*32;
            float sqA = 0.f, sqB = 0.f;
            uint32_t hwA[4], hwB[4];
            #pragma unroll
            for (int j = 0; j < 4; j++) {
                int nt = hg*4 + j;
                int c = cg + j*8 + 2*(lane & 3);
                float b0 = bias[c], b1 = bias[c+1];
                float v0 = acc[mt][nt][0]+b0, v1 = acc[mt][nt][1]+b1;
                float v2 = acc[mt][nt][2]+b0, v3 = acc[mt][nt][3]+b1;
                if (mode == 0) { v0*=scale; v1*=scale; v2*=scale; v3*=scale; }
                sqA += v0*v0 + v1*v1;
                sqB += v2*v2 + v3*v3;
                hwA[j] = pack2(v0, v1);
                hwB[j] = pack2(v2, v3);
            }
            sqA += __shfl_xor_sync(0xffffffffu, sqA, 1);
            sqA += __shfl_xor_sync(0xffffffffu, sqA, 2);
            sqB += __shfl_xor_sync(0xffffffffu, sqB, 1);
            sqB += __shfl_xor_sync(0xffffffffu, sqB, 2);

            uint32_t *dh;
            float* dn = nullptr;
            int hh;
            if (mode == 0)      { hh = cg >> 5;         dh = g_qh; dn = g_qn; }
            else if (cg < 256)  { hh = cg >> 5;         dh = g_kh; dn = g_kn; }
            else                { hh = (cg - 256) >> 5; dh = g_vh; }

            size_t wb = (((size_t)bI*HEADS + hh)*NTOK + nI)*16 + (lane & 3);
            #pragma unroll
            for (int j = 0; j < 4; j++) {
                dh[wb + j*4]        = hwA[j];
                dh[wb + 8*16 + j*4] = hwB[j];
            }
            if (dn && (lane & 3) == 0) {
                size_t nb = ((size_t)bI*HEADS + hh)*NTOK + nI;
                dn[nb]     = sqrtf(sqA);
                dn[nb + 8] = sqrtf(sqB);
            }
        }
    }
}

// ============================================================
// Kernel 2b: output projection GEMM — 3-stage cp.async
// ============================================================
__global__ void __launch_bounds__(256, 2) p_gemm_kernel(
    const float* __restrict__ bias, float* __restrict__ D)
{
    __shared__ alignas(16) char As[3][4096];
    __shared__ alignas(16) char Bs[3][4096];

    int tid = threadIdx.x;
    int lane = tid & 31, wid = tid >> 5;
    int warp_m = wid >> 1, warp_n = wid & 1;
    int row0 = blockIdx.y * 128;
    int col0 = blockIdx.x * 128;
    const int ldb = 256;

    int k_b2 = tid >> 4;
    int n_b2 = (tid & 15) * 8;
    uint32_t offB = (uint32_t)k_b2*256u + (uint32_t)(((n_b2 >> 3) ^ (k_b2 & 7)) << 4);
    uint32_t stB[3], bbase[3];
    #pragma unroll
    for (int s = 0; s < 3; s++) {
        stB[s] = (uint32_t)__cvta_generic_to_shared(&Bs[s][0]) + offB;
        bbase[s] = (uint32_t)__cvta_generic_to_shared(&Bs[s][0]) + (uint32_t)(lane & 15) * 256u;
    }
    int bkm = lane & 7;

    int a_row = tid >> 1;
    int a_u   = tid & 1;
    uint32_t offA = (uint32_t)a_row*32u + (uint32_t)((a_u ^ ((a_row >> 2) & 1)) << 4);
    uint32_t stA[3];
    #pragma unroll
    for (int s = 0; s < 3; s++)
        stA[s] = (uint32_t)__cvta_generic_to_shared(&As[s][0]) + offA;
    const uint32_t* aop = g_aoh + (size_t)(row0 + a_row) * 128 + a_u * 4;

    uint32_t aaddr[3][2];
    {
        int lrow_loc = ((lane >> 3) & 1) * 8 + (lane & 7);
        int lkh = lane >> 4;
        #pragma unroll
        for (int s = 0; s < 3; s++)
            #pragma unroll
            for (int mt = 0; mt < 2; mt++) {
                int m = warp_m * 32 + mt * 16 + lrow_loc;
                uint32_t off = (uint32_t)m * 32u + (uint32_t)((lkh ^ ((m >> 2) & 1)) << 4);
                aaddr[s][mt] = (uint32_t)__cvta_generic_to_shared(&As[s][0]) + off;
            }
    }

    const __half* Bh = g_wh + 196608;

    float acc[2][8][4];
    #pragma unroll
    for (int mt = 0; mt < 2; mt++)
        #pragma unroll
        for (int nt = 0; nt < 8; nt++)
            #pragma unroll
            for (int i = 0; i < 4; i++) acc[mt][nt][i] = 0.f;

#define CPP(kc, s)                                                       \
    {                                                                    \
        cp16(stA[s], aop + (size_t)(kc) * 8);                            \
        cp16(stB[s], Bh + (size_t)((kc)*16 + k_b2) * ldb + col0 + n_b2); \
        cp_commit();                                                     \
    }

    CPP(0, 0)
    CPP(1, 1)

    for (int kc = 0; kc < DIM/16; kc++) {
        int cur = kc % 3;
        cp_wait1();
        __syncthreads();

        uint32_t ah[2][4];
        ldsm_x4(ah[0], aaddr[cur][0]);
        ldsm_x4(ah[1], aaddr[cur][1]);

        #pragma unroll
        for (int nt = 0; nt < 8; nt++) {
            uint32_t boff = (uint32_t)(((warp_n*8 + nt) ^ bkm) << 4);
            uint32_t bh2[2];
            ldsm_x2t(bh2, bbase[cur] + boff);
            mma16816(acc[0][nt], ah[0], bh2);
            mma16816(acc[1][nt], ah[1], bh2);
        }

        if (kc + 2 < DIM/16) {
            int s = (kc + 2) % 3;
            CPP(kc + 2, s)
        } else {
            cp_commit();
        }
    }
#undef CPP

    #pragma unroll
    for (int mt = 0; mt < 2; mt++) {
        int r_base = row0 + warp_m*32 + mt*16 + (lane >> 2);
        #pragma unroll
        for (int nt = 0; nt < 8; nt++) {
            int c = col0 + warp_n*64 + nt*8 + 2*(lane & 3);
            float b0 = bias[c], b1 = bias[c+1];
            *(float2*)&D[(size_t)r_base*DIM + c] =
                make_float2(acc[mt][nt][0]+b0, acc[mt][nt][1]+b1);
            *(float2*)&D[(size_t)(r_base+8)*DIM + c] =
                make_float2(acc[mt][nt][2]+b0, acc[mt][nt][3]+b1);
        }
    }
}

// ============================================================
// Kernel 3: attention — unchanged from R16
// ============================================================
__global__ void __launch_bounds__(128) attn_mma_kernel(const float* __restrict__ mask)
{
    __shared__ alignas(16) char kvsm[8192];
    __shared__ float qn_s[NTOK], kn_s[NTOK];

    int b = blockIdx.x;
    int h = blockIdx.y;
    int w = b & 63;
    int tid = threadIdx.x;
    int lane = tid & 31, wid = tid >> 5;
    int mbase = wid * 16;

    uint32_t kvb = (uint32_t)__cvta_generic_to_shared(kvsm);

    const float* btp = g_bt + (size_t)h*8192;
    const float* mpp = mask + (size_t)w*4096;

    int r_ld = tid >> 1;
    int half = tid & 1;
    int swr = r_ld & 7;
    int ko0 = half * 2;

    size_t wb = (((size_t)b*HEADS + h)*NTOK + r_ld)*16 + half*8;
    size_t nb = ((size_t)b*HEADS + h)*NTOK;

    uint32_t qfh[2][4];
    {
        const uint32_t* qbh = g_qh + nb*16;
        int r0 = mbase + (lane >> 2);
        int wsel = lane & 3;
        #pragma unroll
        for (int kt = 0; kt < 2; kt++) {
            int w0 = kt*8 + wsel;
            qfh[kt][0] = qbh[r0*16 + w0];
            qfh[kt][1] = qbh[(r0+8)*16 + w0];
            qfh[kt][2] = qbh[r0*16 + w0 + 4];
            qfh[kt][3] = qbh[(r0+8)*16 + w0 + 4];
        }
    }

    {
        uint4 a0 = *(const uint4*)(g_kh + wb);
        uint4 a1 = *(const uint4*)(g_kh + wb + 4);
        uint4 b0 = *(const uint4*)(g_vh + wb);
        uint4 b1 = *(const uint4*)(g_vh + wb + 4);
        *(uint4*)(kvsm + r_ld*128 + (((ko0+0) ^ swr) << 4))     = a0;
        *(uint4*)(kvsm + r_ld*128 + (((ko0+1) ^ swr) << 4))     = a1;
        *(uint4*)(kvsm + r_ld*128 + (((4+ko0+0) ^ swr) << 4))   = b0;
        *(uint4*)(kvsm + r_ld*128 + (((4+ko0+1) ^ swr) << 4))   = b1;
        if (tid < 64) qn_s[tid] = g_qn[nb + tid];
        else          kn_s[tid - 64] = g_kn[nb + tid - 64];
    }
    __syncthreads();

    float sf[8][4];
    #pragma unroll
    for (int nt = 0; nt < 8; nt++)
        #pragma unroll
        for (int i = 0; i < 4; i++) sf[nt][i] = 0.f;

    #pragma unroll
    for (int kt = 0; kt < 2; kt++) {
        int krow_l = (lane & 7);
        int kko    = kt*2 + ((lane >> 3) & 1);
        uint32_t kbh[8][2];
        #pragma unroll
        for (int nt = 0; nt < 8; nt++) {
            int krow = nt*8 + krow_l;
            ldsm_x2(kbh[nt], kvb + krow*128 + ((kko ^ (krow & 7)) << 4));
        }
        #pragma unroll
        for (int nt = 0; nt < 8; nt++) mma16816(sf[nt], qfh[kt], kbh[nt]);
    }

    int rA = mbase + (lane >> 2);
    int rB = rA + 8;
    float qnA = qn_s[rA], qnB = qn_s[rB];
    #pragma unroll
    for (int nt = 0; nt < 8; nt++) {
        int c0 = nt*8 + 2*(lane & 3);
        float2 kn2 = *(float2*)&kn_s[c0];
        int iA = rA*64 + c0, iB = rB*64 + c0;
        float4 tbA = *(const float4*)(btp + iA*2);
        float4 tbB = *(const float4*)(btp + iB*2);
        float2 mA = *(const float2*)(mpp + iA);
        float2 mB = *(const float2*)(mpp + iB);
        sf[nt][0] = __fdividef(sf[nt][0], fmaxf(qnA*kn2.x, 1e-6f)) * tbA.x + tbA.y + mA.x;
        sf[nt][1] = __fdividef(sf[nt][1], fmaxf(qnA*kn2.y, 1e-6f)) * tbA.z + tbA.w + mA.y;
        sf[nt][2] = __fdividef(sf[nt][2], fmaxf(qnB*kn2.x, 1e-6f)) * tbB.x + tbB.y + mB.x;
        sf[nt][3] = __fdividef(sf[nt][3], fmaxf(qnB*kn2.y, 1e-6f)) * tbB.z + tbB.w + mB.y;
    }

    {
        float mA = -1e30f, mB = -1e30f;
        #pragma unroll
        for (int nt = 0; nt < 8; nt++) {
            mA = fmaxf(mA, fmaxf(sf[nt][0], sf[nt][1]));
            mB = fmaxf(mB, fmaxf(sf[nt][2], sf[nt][3]));
        }
        mA = fmaxf(mA, __shfl_xor_sync(0xffffffffu, mA, 1));
        mA = fmaxf(mA, __shfl_xor_sync(0xffffffffu, mA, 2));
        mB = fmaxf(mB, __shfl_xor_sync(0xffffffffu, mB, 1));
        mB = fmaxf(mB, __shfl_xor_sync(0xffffffffu, mB, 2));
        float sA = 0.f, sB = 0.f;
        #pragma unroll
        for (int nt = 0; nt < 8; nt++) {
            sf[nt][0] = __expf(sf[nt][0] - mA); sA += sf[nt][0];
            sf[nt][1] = __expf(sf[nt][1] - mA); sA += sf[nt][1];
            sf[nt][2] = __expf(sf[nt][2] - mB); sB += sf[nt][2];
            sf[nt][3] = __expf(sf[nt][3] - mB); sB += sf[nt][3];
        }
        sA += __shfl_xor_sync(0xffffffffu, sA, 1);
        sA += __shfl_xor_sync(0xffffffffu, sA, 2);
        sB += __shfl_xor_sync(0xffffffffu, sB, 1);
        sB += __shfl_xor_sync(0xffffffffu, sB, 2);
        float iA2 = __fdividef(1.f, sA);
        float iB2 = __fdividef(1.f, sB);
        #pragma unroll
        for (int nt = 0; nt < 8; nt++) {
            sf[nt][0] *= iA2; sf[nt][1] *= iA2;
            sf[nt][2] *= iB2; sf[nt][3] *= iB2;
        }
    }

    float of[4][4];
    #pragma unroll
    for (int nt = 0; nt < 4; nt++)
        #pragma unroll
        for (int i = 0; i < 4; i++) of[nt][i] = 0.f;

    #pragma unroll
    for (int kt2 = 0; kt2 < 4; kt2++) {
        int ntA = 2*kt2, ntB = 2*kt2 + 1;
        uint32_t pah[4];
        pah[0] = pack2(sf[ntA][0], sf[ntA][1]);
        pah[1] = pack2(sf[ntA][2], sf[ntA][3]);
        pah[2] = pack2(sf[ntB][0], sf[ntB][1]);
        pah[3] = pack2(sf[ntB][2], sf[ntB][3]);
        int vrow = kt2*16 + (lane & 15);
        int vsw = vrow & 7;
        uint32_t vbh[4][2];
        #pragma unroll
        for (int nt2 = 0; nt2 < 4; nt2++)
            ldsm_x2t(vbh[nt2], kvb + vrow*128 + (((4 + nt2) ^ vsw) << 4));
        #pragma unroll
        for (int nt2 = 0; nt2 < 4; nt2++) mma16816(of[nt2], pah, vbh[nt2]);
    }

    {
        uint32_t* obA = g_aoh + ((size_t)b*NTOK + rA)*128 + h*16 + (lane & 3);
        uint32_t* obB = g_aoh + ((size_t)b*NTOK + rB)*128 + h*16 + (lane & 3);
        #pragma unroll
        for (int nt2 = 0; nt2 < 4; nt2++) {
            obA[nt2*4] = pack2(of[nt2][0], of[nt2][1]);
            obB[nt2*4] = pack2(of[nt2][2], of[nt2][3]);
        }
    }
}

// ============================================================
// launch
// ============================================================
extern "C" void kernel_launch(void* const* d_in, const int* in_sizes, int n_in,
                              void* d_out, int out_size)
{
    const float* x      = (const float*)d_in[0];
    const float* KV     = (const float*)d_in[1];
    const float* mask   = (const float*)d_in[2];
    const float* Wq     = (const float*)d_in[3];
    const float* bq     = (const float*)d_in[4];
    const float* Wkv    = (const float*)d_in[5];
    const float* bkv    = (const float*)d_in[6];
    const float* Wp     = (const float*)d_in[7];
    const float* bp     = (const float*)d_in[8];
    const float* cpb_w1 = (const float*)d_in[9];
    const float* cpb_b1 = (const float*)d_in[10];
    const float* cpb_w2 = (const float*)d_in[11];
    const float* cpb_b2 = (const float*)d_in[12];
    const float* tau    = (const float*)d_in[13];
    const float* lri    = (const float*)d_in[14];
    float* out = (float*)d_out;

    const int MT = (BWIN * NTOK) / 128;   // 1024

    prep_kernel<<<1040 + 32768, 256>>>(Wq, Wkv, Wp, x, KV,
                                       cpb_w1, cpb_b1, cpb_w2, cpb_b2, tau, lri);
    qkv_gemm_kernel<<<dim3(6, MT), 256>>>(bq, bkv);
    attn_mma_kernel<<<dim3(BWIN, HEADS), 128>>>(mask);
    p_gemm_kernel<<<dim3(2, MT), 256>>>(bp, out);
}